// round 1
// baseline (speedup 1.0000x reference)
#include <cuda_runtime.h>
#include <stdint.h>
#include <math.h>

typedef unsigned int u32;
typedef unsigned long long u64;

#define HH 100
#define WWID 152
#define P_TOT 15200
#define NANC 136800
#define NPRE 6000
#define NPOST 300
#define NW 94            // ceil(6000/64)
#define LOC_OFF 0
#define SCORE_OFF 547200
#define ROIS_OFF 820800
#define FS_NEGINF 0x007FFFFFu

// ------------------- scratch (static device globals: no allocation) ---------
__device__ float g_h[512 * P_TOT];          // conv1 output, [oc][p]
__device__ float g_roi[NANC * 4];           // clipped boxes per anchor
__device__ u64   g_keys[NANC];              // (flipped score)<<32 | ~index
__device__ int   g_hist[1024];              // 4 levels x 256 bins
__device__ u32   g_prefix;
__device__ int   g_count_gt;
__device__ int   g_ccount;
__device__ u64   g_cand[8192];
__device__ float g_sboxes[NPRE * 4];        // top-6000 boxes, score order
__device__ unsigned char g_svalid[NPRE + 64];
__device__ u64   g_mask[(size_t)NPRE * NW]; // NMS suppression bitmatrix
__device__ u64   g_keep[NW];
__device__ int   g_keeppre[NW];

// ------------------------------- conv 3x3 -----------------------------------
// Implicit GEMM: out[oc][p] = relu(bias[oc] + sum_{ic,r} W[oc][ic*9+r]*x[ic][p+off(r)])
// Block tile: 64 oc x 64 p, BK = 9 (one input channel per K-step).
__global__ void k_conv(const float* __restrict__ x, const float* __restrict__ w,
                       const float* __restrict__ bias) {
    __shared__ float As[9][68];   // [r][oc_local], padded
    __shared__ float Bs[9][64];   // [r][p_local]
    __shared__ int   spy[64], spx[64];

    const int p0  = blockIdx.x * 64;
    const int oc0 = blockIdx.y * 64;
    const int t   = threadIdx.x;       // 256 threads
    const int tx  = t & 15;            // p direction (4 p each)
    const int ty  = t >> 4;            // oc direction (4 oc each)

    if (t < 64) {
        int pg = p0 + t;
        int yy = pg / WWID;
        spy[t] = yy;
        spx[t] = pg - yy * WWID;
    }
    float acc[4][4];
#pragma unroll
    for (int i = 0; i < 4; i++)
#pragma unroll
        for (int j = 0; j < 4; j++) acc[i][j] = 0.f;
    __syncthreads();

    for (int ic = 0; ic < 512; ic++) {
        // A: weights W[(oc0+i)*4608 + ic*9 + r] -> As[r][i]   (coalesced global)
        const float* wp = w + (size_t)oc0 * 4608 + ic * 9;
#pragma unroll
        for (int e = t; e < 576; e += 256) {
            int i = e / 9;
            int r = e - i * 9;
            As[r][i] = wp[i * 4608 + r];
        }
        // B: im2col x[ic][y+dy][x+dx] -> Bs[r][pl]
        const float* xp = x + ic * P_TOT;
#pragma unroll
        for (int e = t; e < 576; e += 256) {
            int r  = e >> 6;
            int pl = e & 63;
            int yy = spy[pl] + (r / 3) - 1;
            int xx = spx[pl] + (r - (r / 3) * 3) - 1;
            float v = 0.f;
            if (yy >= 0 && yy < HH && xx >= 0 && xx < WWID) v = xp[yy * WWID + xx];
            Bs[r][pl] = v;
        }
        __syncthreads();
#pragma unroll
        for (int kk = 0; kk < 9; kk++) {
            float4 av = *(const float4*)&As[kk][ty * 4];
            float4 bv = *(const float4*)&Bs[kk][tx * 4];
            float a4[4] = {av.x, av.y, av.z, av.w};
            float b4[4] = {bv.x, bv.y, bv.z, bv.w};
#pragma unroll
            for (int i = 0; i < 4; i++)
#pragma unroll
                for (int j = 0; j < 4; j++) acc[i][j] += a4[i] * b4[j];
        }
        __syncthreads();
    }
#pragma unroll
    for (int i = 0; i < 4; i++) {
        int oc = oc0 + ty * 4 + i;
        float bb = bias[oc];
#pragma unroll
        for (int j = 0; j < 4; j++) {
            int p = p0 + tx * 4 + j;
            if (p < P_TOT) g_h[(size_t)oc * P_TOT + p] = fmaxf(acc[i][j] + bb, 0.f);
        }
    }
}

// ------------------------------- heads (1x1 convs) ---------------------------
// 54 output channels (18 score + 36 loc) per pixel; writes rpn_loc / rpn_score
// directly into d_out with the NHWC-reshape layout of the reference.
__global__ void k_heads(const float* __restrict__ sw, const float* __restrict__ sb,
                        const float* __restrict__ lw, const float* __restrict__ lb,
                        float* __restrict__ out) {
    __shared__ float hs[16][68];   // [p_local][c_chunk]
    __shared__ float ws[54][68];   // [ch][c_chunk]
    const int p0 = blockIdx.x * 16;
    const int t  = threadIdx.x;    // 864 threads
    const int pl = t & 15;
    const int ch = t >> 4;         // 0..53
    float acc = 0.f;

    for (int c0 = 0; c0 < 512; c0 += 64) {
        for (int e = t; e < 54 * 64; e += 864) {
            int cc  = e & 63;
            int chh = e >> 6;
            float v = (chh < 18) ? sw[chh * 512 + c0 + cc]
                                 : lw[(chh - 18) * 512 + c0 + cc];
            ws[chh][cc] = v;
        }
        for (int e = t; e < 16 * 64; e += 864) {
            int pp = e & 15;
            int cc = e >> 4;
            hs[pp][cc] = g_h[(size_t)(c0 + cc) * P_TOT + p0 + pp];
        }
        __syncthreads();
#pragma unroll
        for (int c4 = 0; c4 < 64; c4 += 4) {
            float4 wv = *(const float4*)&ws[ch][c4];
            float4 hv = *(const float4*)&hs[pl][c4];
            acc += wv.x * hv.x + wv.y * hv.y + wv.z * hv.z + wv.w * hv.w;
        }
        __syncthreads();
    }
    int pg = p0 + pl;   // always < 15200 (950*16 = 15200)
    if (ch < 18) {
        acc += sb[ch];
        int anc = ch >> 1, d = ch & 1;
        out[SCORE_OFF + ((size_t)pg * 9 + anc) * 2 + d] = acc;
    } else {
        int lc = ch - 18;
        acc += lb[lc];
        int anc = lc >> 2, d = lc & 3;
        out[LOC_OFF + ((size_t)pg * 9 + anc) * 4 + d] = acc;
    }
}

// ------------------------------- proposals -----------------------------------
__device__ __forceinline__ float scal_to_f(const int* p) {
    int v = *p;
    if (v > 0 && v < 10000000) return (float)v;   // int32 scalar
    return __int_as_float(v);                     // float32 scalar fallback
}

__global__ void k_prop(const float* __restrict__ out, const int* ihp, const int* iwp) {
    int a = blockIdx.x * 256 + threadIdx.x;
    if (a >= NANC) return;
    float imh = scal_to_f(ihp);
    float imw = scal_to_f(iwp);

    int t  = a % 9;
    int p  = a / 9;
    int y  = p / WWID;
    int xi = p - y * WWID;
    int ri = t / 3, si = t - ri * 3;
    double r = (ri == 0) ? 0.5 : (ri == 1 ? 1.0 : 2.0);
    double s = (si == 0) ? 8.0 : (si == 1 ? 16.0 : 32.0);
    double hbd = 16.0 * s * sqrt(r);
    double wbd = 16.0 * s * sqrt(1.0 / r);
    float ay1 = (float)y * 16.f + (float)(8.0 - hbd / 2.0);
    float ax1 = (float)xi * 16.f + (float)(8.0 - wbd / 2.0);
    float ay2 = (float)y * 16.f + (float)(8.0 + hbd / 2.0);
    float ax2 = (float)xi * 16.f + (float)(8.0 + wbd / 2.0);

    float dy = out[LOC_OFF + (size_t)a * 4 + 0];
    float dx = out[LOC_OFF + (size_t)a * 4 + 1];
    float dh = out[LOC_OFF + (size_t)a * 4 + 2];
    float dw = out[LOC_OFF + (size_t)a * 4 + 3];

    float ah = ay2 - ay1, aw = ax2 - ax1;
    float cy = ay1 + 0.5f * ah, cx = ax1 + 0.5f * aw;
    float cy2 = dy * ah + cy, cx2 = dx * aw + cx;
    float h2 = expf(dh) * ah, w2 = expf(dw) * aw;
    float r0 = cy2 - 0.5f * h2, r1 = cx2 - 0.5f * w2;
    float r2 = cy2 + 0.5f * h2, r3 = cx2 + 0.5f * w2;
    r0 = fminf(fmaxf(r0, 0.f), imh);
    r1 = fminf(fmaxf(r1, 0.f), imw);
    r2 = fminf(fmaxf(r2, 0.f), imh);
    r3 = fminf(fmaxf(r3, 0.f), imw);
    bool valid = (r2 - r0 >= 16.f) && (r3 - r1 >= 16.f);

    float s0 = out[SCORE_OFF + (size_t)a * 2 + 0];
    float s1 = out[SCORE_OFF + (size_t)a * 2 + 1];
    float m = fmaxf(s0, s1);
    float e0 = expf(s0 - m), e1 = expf(s1 - m);
    float fg = e1 / (e0 + e1);
    float sc = valid ? fg : __int_as_float(0xff800000);

    u32 bits = __float_as_uint(sc);
    u32 fs = bits ^ ((bits & 0x80000000u) ? 0xFFFFFFFFu : 0x80000000u);
    g_keys[a] = ((u64)fs << 32) | (u32)(~(u32)a);
    g_roi[(size_t)a * 4 + 0] = r0;
    g_roi[(size_t)a * 4 + 1] = r1;
    g_roi[(size_t)a * 4 + 2] = r2;
    g_roi[(size_t)a * 4 + 3] = r3;
}

// --------------------- top-6000 selection (radix select) ---------------------
__global__ void k_clear() {
    int t = threadIdx.x;
    if (t < 1024) g_hist[t] = 0;
    if (t == 0) { g_prefix = 0u; g_count_gt = 0; g_ccount = 0; }
}

__global__ void k_hist(int L) {
    __shared__ int sh[256];
    int t = threadIdx.x;
    sh[t] = 0;
    __syncthreads();
    int idx = blockIdx.x * 256 + t;
    if (idx < NANC) {
        u32 fs = (u32)(g_keys[idx] >> 32);
        bool ok = true;
        if (L > 0) {
            int shf = 32 - 8 * L;
            ok = (fs >> shf) == (g_prefix >> shf);
        }
        if (ok) atomicAdd(&sh[(fs >> (24 - 8 * L)) & 255], 1);
    }
    __syncthreads();
    if (sh[t]) atomicAdd(&g_hist[L * 256 + t], sh[t]);
}

__global__ void k_scan(int L) {
    int need = NPRE - g_count_gt;
    int above = 0;
    int chosen = 0;
    for (int b = 255; b >= 0; b--) {
        int c = g_hist[L * 256 + b];
        if (above + c >= need) { chosen = b; break; }
        above += c;
    }
    g_prefix |= (u32)chosen << (24 - 8 * L);
    g_count_gt += above;
}

__global__ void k_compact() {
    int idx = blockIdx.x * 256 + threadIdx.x;
    if (idx >= NANC) return;
    u64 key = g_keys[idx];
    u32 fs = (u32)(key >> 32);
    if (fs >= g_prefix) {
        int pos = atomicAdd(&g_ccount, 1);
        if (pos < 8192) g_cand[pos] = key;
    }
}

// One-block bitonic sort (descending) of <=8192 candidate keys.
__global__ void k_sort(float* __restrict__ out) {
    extern __shared__ u64 sk[];
    int t = threadIdx.x;   // 1024
    int C = g_ccount;
    if (C > 8192) C = 8192;
    for (int i = t; i < 8192; i += 1024) sk[i] = (i < C) ? g_cand[i] : 0ULL;
    __syncthreads();
    for (int k = 2; k <= 8192; k <<= 1) {
        for (int j = k >> 1; j > 0; j >>= 1) {
            for (int i = t; i < 8192; i += 1024) {
                int ixj = i ^ j;
                if (ixj > i) {
                    u64 a = sk[i], b = sk[ixj];
                    bool descBlock = ((i & k) == 0);
                    bool sw = descBlock ? (a < b) : (a > b);
                    if (sw) { sk[i] = b; sk[ixj] = a; }
                }
            }
            __syncthreads();
        }
    }
    for (int i = t; i < NPRE; i += 1024) {
        u64 key = sk[i];
        u32 fs = (u32)(key >> 32);
        u32 idx = ~(u32)key;
        float b0 = 0.f, b1 = 0.f, b2 = 0.f, b3 = 0.f;
        if (key != 0ULL && idx < NANC) {
            b0 = g_roi[(size_t)idx * 4 + 0];
            b1 = g_roi[(size_t)idx * 4 + 1];
            b2 = g_roi[(size_t)idx * 4 + 2];
            b3 = g_roi[(size_t)idx * 4 + 3];
        }
        g_sboxes[i * 4 + 0] = b0;
        g_sboxes[i * 4 + 1] = b1;
        g_sboxes[i * 4 + 2] = b2;
        g_sboxes[i * 4 + 3] = b3;
        g_svalid[i] = (fs > FS_NEGINF) ? 1 : 0;
    }
    // zero the rois output region (written sparsely by k_final)
    for (int i = t; i < NPOST * 4; i += 1024) out[ROIS_OFF + i] = 0.f;
}

// ------------------------------- NMS -----------------------------------------
__global__ void k_mask() {
    __shared__ float cy1[64], cx1[64], cy2s[64], cx2s[64], car[64];
    int t = threadIdx.x;
    int bi = blockIdx.y, bj = blockIdx.x;
    int j = bj * 64 + t;
    float jy1 = 0, jx1 = 0, jy2 = 0, jx2 = 0;
    if (j < NPRE) {
        jy1 = g_sboxes[j * 4 + 0];
        jx1 = g_sboxes[j * 4 + 1];
        jy2 = g_sboxes[j * 4 + 2];
        jx2 = g_sboxes[j * 4 + 3];
    }
    cy1[t] = jy1; cx1[t] = jx1; cy2s[t] = jy2; cx2s[t] = jx2;
    car[t] = (jy2 - jy1) * (jx2 - jx1);
    __syncthreads();
    int i = bi * 64 + t;
    if (i >= NPRE) return;
    float iy1 = g_sboxes[i * 4 + 0];
    float ix1 = g_sboxes[i * 4 + 1];
    float iy2 = g_sboxes[i * 4 + 2];
    float ix2 = g_sboxes[i * 4 + 3];
    float ar = (iy2 - iy1) * (ix2 - ix1);
    u64 word = 0;
#pragma unroll 8
    for (int jj = 0; jj < 64; jj++) {
        int jg = bj * 64 + jj;
        float ih = fmaxf(fminf(iy2, cy2s[jj]) - fmaxf(iy1, cy1[jj]), 0.f);
        float iw = fmaxf(fminf(ix2, cx2s[jj]) - fmaxf(ix1, cx1[jj]), 0.f);
        float inter = ih * iw;
        float iou = inter / (ar + car[jj] - inter + 1e-9f);
        if (jg > i && jg < NPRE && iou > 0.7f) word |= 1ULL << jj;
    }
    g_mask[(size_t)i * NW + bj] = word;
}

__device__ __forceinline__ u64 apply_valid(int w, u64 k) {
    int base = w * 64;
#pragma unroll 4
    for (int b = 0; b < 64; b++) {
        int row = base + b;
        if (row >= NPRE || !g_svalid[row]) k &= ~(1ULL << b);
    }
    return k;
}

__global__ void k_reduce() {
    int l = threadIdx.x;   // 32 lanes; lane owns words l, l+32, l+64
    u64 k0 = ~0ULL;
    u64 k1 = ~0ULL;
    u64 k2;
    {
        int w = l + 64;
        if (w < 93) k2 = ~0ULL;
        else if (w == 93) k2 = 0x0000FFFFFFFFFFFFULL;  // rows 5952..5999
        else k2 = 0ULL;
    }
    for (int i = 0; i < NPRE; i++) {
        int w = i >> 6;
        int slot = w >> 5;
        int src = w & 31;
        u64 kv = (slot == 0) ? k0 : ((slot == 1) ? k1 : k2);
        u64 kw = __shfl_sync(0xffffffffu, kv, src);
        if ((kw >> (i & 63)) & 1ULL) {
            const u64* mr = g_mask + (size_t)i * NW;
            u64 m0 = mr[l];
            u64 m1 = mr[l + 32];
            u64 m2 = (l + 64 < NW) ? mr[l + 64] : 0ULL;
            k0 &= ~m0;
            k1 &= ~m1;
            k2 &= ~m2;
        }
    }
    g_keep[l]      = apply_valid(l, k0);
    g_keep[l + 32] = apply_valid(l + 32, k1);
    if (l + 64 < NW) g_keep[l + 64] = apply_valid(l + 64, k2);
    __syncwarp();
    if (l == 0) {
        int run = 0;
        for (int w = 0; w < NW; w++) {
            g_keeppre[w] = run;
            run += __popcll(g_keep[w]);
        }
    }
}

__global__ void k_final(float* __restrict__ out) {
    int i = blockIdx.x * 256 + threadIdx.x;
    if (i >= NPRE) return;
    int w = i >> 6, b = i & 63;
    u64 kw = g_keep[w];
    if (!((kw >> b) & 1ULL)) return;
    u64 below = kw & ((1ULL << b) - 1ULL);
    int pos = g_keeppre[w] + __popcll(below);
    if (pos < NPOST) {
        out[ROIS_OFF + pos * 4 + 0] = g_sboxes[i * 4 + 0];
        out[ROIS_OFF + pos * 4 + 1] = g_sboxes[i * 4 + 1];
        out[ROIS_OFF + pos * 4 + 2] = g_sboxes[i * 4 + 2];
        out[ROIS_OFF + pos * 4 + 3] = g_sboxes[i * 4 + 3];
    }
}

// ------------------------------- launch --------------------------------------
extern "C" void kernel_launch(void* const* d_in, const int* in_sizes, int n_in,
                              void* d_out, int out_size) {
    const float* x  = (const float*)d_in[0];
    const float* w1 = (const float*)d_in[1];
    const float* b1 = (const float*)d_in[2];
    const float* sw = (const float*)d_in[3];
    const float* sb = (const float*)d_in[4];
    const float* lw = (const float*)d_in[5];
    const float* lb = (const float*)d_in[6];
    const int* ihp  = (const int*)d_in[7];
    const int* iwp  = (const int*)d_in[8];
    float* out = (float*)d_out;

    k_conv<<<dim3(238, 8), 256>>>(x, w1, b1);
    k_heads<<<950, 864>>>(sw, sb, lw, lb, out);
    k_prop<<<(NANC + 255) / 256, 256>>>(out, ihp, iwp);

    k_clear<<<1, 1024>>>();
    for (int L = 0; L < 4; L++) {
        k_hist<<<(NANC + 255) / 256, 256>>>(L);
        k_scan<<<1, 1>>>(L);
    }
    k_compact<<<(NANC + 255) / 256, 256>>>();

    cudaFuncSetAttribute(k_sort, cudaFuncAttributeMaxDynamicSharedMemorySize, 65536);
    k_sort<<<1, 1024, 65536>>>(out);

    k_mask<<<dim3(NW, NW), 64>>>();
    k_reduce<<<1, 32>>>();
    k_final<<<(NPRE + 255) / 256, 256>>>(out);
}

// round 2
// speedup vs baseline: 1.3270x; 1.3270x over previous
#include <cuda_runtime.h>
#include <stdint.h>
#include <math.h>

typedef unsigned int u32;
typedef unsigned long long u64;

#define HH 100
#define WWID 152
#define P_TOT 15200
#define NANC 136800
#define NPRE 6000
#define NPOST 300
#define NW 94            // ceil(6000/64)
#define LOC_OFF 0
#define SCORE_OFF 547200
#define ROIS_OFF 820800
#define FS_NEGINF 0x007FFFFFu

// ------------------- scratch (static device globals: no allocation) ---------
__device__ float g_h[512 * P_TOT];          // conv1 output, [oc][p]
__device__ float g_roi[NANC * 4];           // clipped boxes per anchor
__device__ u64   g_keys[NANC];              // (flipped score)<<32 | ~index
__device__ int   g_hist[1024];              // 4 levels x 256 bins
__device__ u32   g_prefix;
__device__ int   g_count_gt;
__device__ int   g_ccount;
__device__ u64   g_cand[8192];
__device__ float g_sboxes[NPRE * 4];        // top-6000 boxes, score order
__device__ unsigned char g_svalid[NPRE + 64];
__device__ u64   g_mask[(size_t)NPRE * NW]; // NMS suppression bitmatrix
__device__ u64   g_keep[NW];
__device__ int   g_keeppre[NW];

// ------------------------------- conv 3x3 -----------------------------------
// Implicit GEMM, 128(oc) x 128(p) block tile, 8x8 per-thread register tile,
// BK = 9 (one input channel per K-step). Per kk: 4 LDS.128 feed 64 FFMA.
__global__ void __launch_bounds__(256, 2)
k_conv(const float* __restrict__ x, const float* __restrict__ w,
       const float* __restrict__ bias) {
    __shared__ float As[9][132];   // [r][oc_local], padded stride
    __shared__ float Bs[9][128];   // [r][p_local]

    const int p0  = blockIdx.x * 128;
    const int oc0 = blockIdx.y * 128;
    const int t   = threadIdx.x;       // 256 threads
    const int tx  = t & 15;            // p direction (8 p each)
    const int ty  = t >> 4;            // oc direction (8 oc each)

    float* Asf = &As[0][0];
    float* Bsf = &Bs[0][0];

    // Precompute per-thread load slots (1152 elements each for A and B, 4.5/thread)
    int awoff[5], asto[5];             // A: gmem base offset, smem store offset
    int bgoff[5], bsto[5];             // B: gmem offset (im2col), smem store offset
    bool bval[5], sval[5];
#pragma unroll
    for (int s = 0; s < 5; s++) {
        int e = t + s * 256;
        sval[s] = (e < 1152);
        int ee = sval[s] ? e : 0;
        // A slot: e -> (i = e/9 oc row, r = e%9)
        int i = ee / 9;
        int r = ee - i * 9;
        awoff[s] = (oc0 + i) * 4608 + r;
        asto[s]  = r * 132 + i;
        // B slot: e -> (r = e/128, pl = e%128)
        int br = ee >> 7;
        int pl = ee & 127;
        int pg = p0 + pl;
        int y  = pg / WWID;
        int xx = pg - y * WWID;
        int yy = y + (br / 3) - 1;
        int x2 = xx + (br - (br / 3) * 3) - 1;
        bval[s]  = sval[s] && (pg < P_TOT) && (yy >= 0) && (yy < HH) && (x2 >= 0) && (x2 < WWID);
        bgoff[s] = bval[s] ? (yy * WWID + x2) : 0;
        bsto[s]  = br * 128 + pl;
    }

    float acc[8][8];
#pragma unroll
    for (int i = 0; i < 8; i++)
#pragma unroll
        for (int j = 0; j < 8; j++) acc[i][j] = 0.f;

    for (int ic = 0; ic < 512; ic++) {
        const float* xp = x + (size_t)ic * P_TOT;
        int kbase = ic * 9;
#pragma unroll
        for (int s = 0; s < 5; s++) {
            if (sval[s]) {
                Asf[asto[s]] = __ldg(&w[awoff[s] + kbase]);
                Bsf[bsto[s]] = bval[s] ? __ldg(&xp[bgoff[s]]) : 0.f;
            }
        }
        __syncthreads();
#pragma unroll
        for (int kk = 0; kk < 9; kk++) {
            float a[8], b[8];
            *(float4*)&a[0] = *(const float4*)&As[kk][ty * 8];
            *(float4*)&a[4] = *(const float4*)&As[kk][ty * 8 + 4];
            *(float4*)&b[0] = *(const float4*)&Bs[kk][tx * 8];
            *(float4*)&b[4] = *(const float4*)&Bs[kk][tx * 8 + 4];
#pragma unroll
            for (int i = 0; i < 8; i++)
#pragma unroll
                for (int j = 0; j < 8; j++) acc[i][j] += a[i] * b[j];
        }
        __syncthreads();
    }
#pragma unroll
    for (int i = 0; i < 8; i++) {
        int oc = oc0 + ty * 8 + i;
        float bb = bias[oc];
        float* gp = g_h + (size_t)oc * P_TOT;
#pragma unroll
        for (int j4 = 0; j4 < 8; j4 += 4) {
            int p = p0 + tx * 8 + j4;
            if (p < P_TOT) {
                float4 v;
                v.x = fmaxf(acc[i][j4 + 0] + bb, 0.f);
                v.y = fmaxf(acc[i][j4 + 1] + bb, 0.f);
                v.z = fmaxf(acc[i][j4 + 2] + bb, 0.f);
                v.w = fmaxf(acc[i][j4 + 3] + bb, 0.f);
                *(float4*)&gp[p] = v;
            }
        }
    }
}

// ------------------------------- heads (1x1 convs) ---------------------------
__global__ void k_heads(const float* __restrict__ sw, const float* __restrict__ sb,
                        const float* __restrict__ lw, const float* __restrict__ lb,
                        float* __restrict__ out) {
    __shared__ float hs[16][68];   // [p_local][c_chunk]
    __shared__ float ws[54][68];   // [ch][c_chunk]
    const int p0 = blockIdx.x * 16;
    const int t  = threadIdx.x;    // 864 threads
    const int pl = t & 15;
    const int ch = t >> 4;         // 0..53
    float acc = 0.f;

    for (int c0 = 0; c0 < 512; c0 += 64) {
        for (int e = t; e < 54 * 64; e += 864) {
            int cc  = e & 63;
            int chh = e >> 6;
            float v = (chh < 18) ? sw[chh * 512 + c0 + cc]
                                 : lw[(chh - 18) * 512 + c0 + cc];
            ws[chh][cc] = v;
        }
        for (int e = t; e < 16 * 64; e += 864) {
            int pp = e & 15;
            int cc = e >> 4;
            hs[pp][cc] = g_h[(size_t)(c0 + cc) * P_TOT + p0 + pp];
        }
        __syncthreads();
#pragma unroll
        for (int c4 = 0; c4 < 64; c4 += 4) {
            float4 wv = *(const float4*)&ws[ch][c4];
            float4 hv = *(const float4*)&hs[pl][c4];
            acc += wv.x * hv.x + wv.y * hv.y + wv.z * hv.z + wv.w * hv.w;
        }
        __syncthreads();
    }
    int pg = p0 + pl;   // always < 15200 (950*16 = 15200)
    if (ch < 18) {
        acc += sb[ch];
        int anc = ch >> 1, d = ch & 1;
        out[SCORE_OFF + ((size_t)pg * 9 + anc) * 2 + d] = acc;
    } else {
        int lc = ch - 18;
        acc += lb[lc];
        int anc = lc >> 2, d = lc & 3;
        out[LOC_OFF + ((size_t)pg * 9 + anc) * 4 + d] = acc;
    }
}

// ------------------------------- proposals -----------------------------------
__device__ __forceinline__ float scal_to_f(const int* p) {
    int v = *p;
    if (v > 0 && v < 10000000) return (float)v;   // int32 scalar
    return __int_as_float(v);                     // float32 scalar fallback
}

__global__ void k_prop(const float* __restrict__ out, const int* ihp, const int* iwp) {
    int a = blockIdx.x * 256 + threadIdx.x;
    if (a >= NANC) return;
    float imh = scal_to_f(ihp);
    float imw = scal_to_f(iwp);

    int t  = a % 9;
    int p  = a / 9;
    int y  = p / WWID;
    int xi = p - y * WWID;
    int ri = t / 3, si = t - ri * 3;
    double r = (ri == 0) ? 0.5 : (ri == 1 ? 1.0 : 2.0);
    double s = (si == 0) ? 8.0 : (si == 1 ? 16.0 : 32.0);
    double hbd = 16.0 * s * sqrt(r);
    double wbd = 16.0 * s * sqrt(1.0 / r);
    float ay1 = (float)y * 16.f + (float)(8.0 - hbd / 2.0);
    float ax1 = (float)xi * 16.f + (float)(8.0 - wbd / 2.0);
    float ay2 = (float)y * 16.f + (float)(8.0 + hbd / 2.0);
    float ax2 = (float)xi * 16.f + (float)(8.0 + wbd / 2.0);

    float dy = out[LOC_OFF + (size_t)a * 4 + 0];
    float dx = out[LOC_OFF + (size_t)a * 4 + 1];
    float dh = out[LOC_OFF + (size_t)a * 4 + 2];
    float dw = out[LOC_OFF + (size_t)a * 4 + 3];

    float ah = ay2 - ay1, aw = ax2 - ax1;
    float cy = ay1 + 0.5f * ah, cx = ax1 + 0.5f * aw;
    float cy2 = dy * ah + cy, cx2 = dx * aw + cx;
    float h2 = expf(dh) * ah, w2 = expf(dw) * aw;
    float r0 = cy2 - 0.5f * h2, r1 = cx2 - 0.5f * w2;
    float r2 = cy2 + 0.5f * h2, r3 = cx2 + 0.5f * w2;
    r0 = fminf(fmaxf(r0, 0.f), imh);
    r1 = fminf(fmaxf(r1, 0.f), imw);
    r2 = fminf(fmaxf(r2, 0.f), imh);
    r3 = fminf(fmaxf(r3, 0.f), imw);
    bool valid = (r2 - r0 >= 16.f) && (r3 - r1 >= 16.f);

    float s0 = out[SCORE_OFF + (size_t)a * 2 + 0];
    float s1 = out[SCORE_OFF + (size_t)a * 2 + 1];
    float m = fmaxf(s0, s1);
    float e0 = expf(s0 - m), e1 = expf(s1 - m);
    float fg = e1 / (e0 + e1);
    float sc = valid ? fg : __int_as_float(0xff800000);

    u32 bits = __float_as_uint(sc);
    u32 fs = bits ^ ((bits & 0x80000000u) ? 0xFFFFFFFFu : 0x80000000u);
    g_keys[a] = ((u64)fs << 32) | (u32)(~(u32)a);
    g_roi[(size_t)a * 4 + 0] = r0;
    g_roi[(size_t)a * 4 + 1] = r1;
    g_roi[(size_t)a * 4 + 2] = r2;
    g_roi[(size_t)a * 4 + 3] = r3;
}

// --------------------- top-6000 selection (radix select) ---------------------
__global__ void k_clear() {
    int t = threadIdx.x;
    if (t < 1024) g_hist[t] = 0;
    if (t == 0) { g_prefix = 0u; g_count_gt = 0; g_ccount = 0; }
}

__global__ void k_hist(int L) {
    __shared__ int sh[256];
    int t = threadIdx.x;
    sh[t] = 0;
    __syncthreads();
    int idx = blockIdx.x * 256 + t;
    if (idx < NANC) {
        u32 fs = (u32)(g_keys[idx] >> 32);
        bool ok = true;
        if (L > 0) {
            int shf = 32 - 8 * L;
            ok = (fs >> shf) == (g_prefix >> shf);
        }
        if (ok) atomicAdd(&sh[(fs >> (24 - 8 * L)) & 255], 1);
    }
    __syncthreads();
    if (sh[t]) atomicAdd(&g_hist[L * 256 + t], sh[t]);
}

__global__ void k_scan(int L) {
    int need = NPRE - g_count_gt;
    int above = 0;
    int chosen = 0;
    for (int b = 255; b >= 0; b--) {
        int c = g_hist[L * 256 + b];
        if (above + c >= need) { chosen = b; break; }
        above += c;
    }
    g_prefix |= (u32)chosen << (24 - 8 * L);
    g_count_gt += above;
}

__global__ void k_compact() {
    int idx = blockIdx.x * 256 + threadIdx.x;
    if (idx >= NANC) return;
    u64 key = g_keys[idx];
    u32 fs = (u32)(key >> 32);
    if (fs >= g_prefix) {
        int pos = atomicAdd(&g_ccount, 1);
        if (pos < 8192) g_cand[pos] = key;
    }
}

// One-block bitonic sort (descending) of <=8192 candidate keys.
__global__ void k_sort(float* __restrict__ out) {
    extern __shared__ u64 sk[];
    int t = threadIdx.x;   // 1024
    int C = g_ccount;
    if (C > 8192) C = 8192;
    for (int i = t; i < 8192; i += 1024) sk[i] = (i < C) ? g_cand[i] : 0ULL;
    __syncthreads();
    for (int k = 2; k <= 8192; k <<= 1) {
        for (int j = k >> 1; j > 0; j >>= 1) {
            for (int i = t; i < 8192; i += 1024) {
                int ixj = i ^ j;
                if (ixj > i) {
                    u64 a = sk[i], b = sk[ixj];
                    bool descBlock = ((i & k) == 0);
                    bool sw = descBlock ? (a < b) : (a > b);
                    if (sw) { sk[i] = b; sk[ixj] = a; }
                }
            }
            __syncthreads();
        }
    }
    for (int i = t; i < NPRE; i += 1024) {
        u64 key = sk[i];
        u32 fs = (u32)(key >> 32);
        u32 idx = ~(u32)key;
        float b0 = 0.f, b1 = 0.f, b2 = 0.f, b3 = 0.f;
        if (key != 0ULL && idx < NANC) {
            b0 = g_roi[(size_t)idx * 4 + 0];
            b1 = g_roi[(size_t)idx * 4 + 1];
            b2 = g_roi[(size_t)idx * 4 + 2];
            b3 = g_roi[(size_t)idx * 4 + 3];
        }
        g_sboxes[i * 4 + 0] = b0;
        g_sboxes[i * 4 + 1] = b1;
        g_sboxes[i * 4 + 2] = b2;
        g_sboxes[i * 4 + 3] = b3;
        g_svalid[i] = (fs > FS_NEGINF) ? 1 : 0;
    }
    // zero the rois output region (written sparsely by k_final)
    for (int i = t; i < NPOST * 4; i += 1024) out[ROIS_OFF + i] = 0.f;
}

// ------------------------------- NMS -----------------------------------------
__global__ void k_mask() {
    __shared__ float cy1[64], cx1[64], cy2s[64], cx2s[64], car[64];
    int t = threadIdx.x;
    int bi = blockIdx.y, bj = blockIdx.x;
    int j = bj * 64 + t;
    float jy1 = 0, jx1 = 0, jy2 = 0, jx2 = 0;
    if (j < NPRE) {
        jy1 = g_sboxes[j * 4 + 0];
        jx1 = g_sboxes[j * 4 + 1];
        jy2 = g_sboxes[j * 4 + 2];
        jx2 = g_sboxes[j * 4 + 3];
    }
    cy1[t] = jy1; cx1[t] = jx1; cy2s[t] = jy2; cx2s[t] = jx2;
    car[t] = (jy2 - jy1) * (jx2 - jx1);
    __syncthreads();
    int i = bi * 64 + t;
    if (i >= NPRE) return;
    float iy1 = g_sboxes[i * 4 + 0];
    float ix1 = g_sboxes[i * 4 + 1];
    float iy2 = g_sboxes[i * 4 + 2];
    float ix2 = g_sboxes[i * 4 + 3];
    float ar = (iy2 - iy1) * (ix2 - ix1);
    u64 word = 0;
#pragma unroll 8
    for (int jj = 0; jj < 64; jj++) {
        int jg = bj * 64 + jj;
        float ih = fmaxf(fminf(iy2, cy2s[jj]) - fmaxf(iy1, cy1[jj]), 0.f);
        float iw = fmaxf(fminf(ix2, cx2s[jj]) - fmaxf(ix1, cx1[jj]), 0.f);
        float inter = ih * iw;
        float iou = inter / (ar + car[jj] - inter + 1e-9f);
        if (jg > i && jg < NPRE && iou > 0.7f) word |= 1ULL << jj;
    }
    g_mask[(size_t)i * NW + bj] = word;
}

__device__ __forceinline__ u64 apply_valid(int w, u64 k) {
    int base = w * 64;
#pragma unroll 4
    for (int b = 0; b < 64; b++) {
        int row = base + b;
        if (row >= NPRE || !g_svalid[row]) k &= ~(1ULL << b);
    }
    return k;
}

__global__ void k_reduce() {
    int l = threadIdx.x;   // 32 lanes; lane owns words l, l+32, l+64
    u64 k0 = ~0ULL;
    u64 k1 = ~0ULL;
    u64 k2;
    {
        int w = l + 64;
        if (w < 93) k2 = ~0ULL;
        else if (w == 93) k2 = 0x0000FFFFFFFFFFFFULL;  // rows 5952..5999
        else k2 = 0ULL;
    }
    for (int i = 0; i < NPRE; i++) {
        int w = i >> 6;
        int slot = w >> 5;
        int src = w & 31;
        u64 kv = (slot == 0) ? k0 : ((slot == 1) ? k1 : k2);
        u64 kw = __shfl_sync(0xffffffffu, kv, src);
        if ((kw >> (i & 63)) & 1ULL) {
            const u64* mr = g_mask + (size_t)i * NW;
            u64 m0 = mr[l];
            u64 m1 = mr[l + 32];
            u64 m2 = (l + 64 < NW) ? mr[l + 64] : 0ULL;
            k0 &= ~m0;
            k1 &= ~m1;
            k2 &= ~m2;
        }
    }
    g_keep[l]      = apply_valid(l, k0);
    g_keep[l + 32] = apply_valid(l + 32, k1);
    if (l + 64 < NW) g_keep[l + 64] = apply_valid(l + 64, k2);
    __syncwarp();
    if (l == 0) {
        int run = 0;
        for (int w = 0; w < NW; w++) {
            g_keeppre[w] = run;
            run += __popcll(g_keep[w]);
        }
    }
}

__global__ void k_final(float* __restrict__ out) {
    int i = blockIdx.x * 256 + threadIdx.x;
    if (i >= NPRE) return;
    int w = i >> 6, b = i & 63;
    u64 kw = g_keep[w];
    if (!((kw >> b) & 1ULL)) return;
    u64 below = kw & ((1ULL << b) - 1ULL);
    int pos = g_keeppre[w] + __popcll(below);
    if (pos < NPOST) {
        out[ROIS_OFF + pos * 4 + 0] = g_sboxes[i * 4 + 0];
        out[ROIS_OFF + pos * 4 + 1] = g_sboxes[i * 4 + 1];
        out[ROIS_OFF + pos * 4 + 2] = g_sboxes[i * 4 + 2];
        out[ROIS_OFF + pos * 4 + 3] = g_sboxes[i * 4 + 3];
    }
}

// ------------------------------- launch --------------------------------------
extern "C" void kernel_launch(void* const* d_in, const int* in_sizes, int n_in,
                              void* d_out, int out_size) {
    const float* x  = (const float*)d_in[0];
    const float* w1 = (const float*)d_in[1];
    const float* b1 = (const float*)d_in[2];
    const float* sw = (const float*)d_in[3];
    const float* sb = (const float*)d_in[4];
    const float* lw = (const float*)d_in[5];
    const float* lb = (const float*)d_in[6];
    const int* ihp  = (const int*)d_in[7];
    const int* iwp  = (const int*)d_in[8];
    float* out = (float*)d_out;

    k_conv<<<dim3(119, 4), 256>>>(x, w1, b1);
    k_heads<<<950, 864>>>(sw, sb, lw, lb, out);
    k_prop<<<(NANC + 255) / 256, 256>>>(out, ihp, iwp);

    k_clear<<<1, 1024>>>();
    for (int L = 0; L < 4; L++) {
        k_hist<<<(NANC + 255) / 256, 256>>>(L);
        k_scan<<<1, 1>>>(L);
    }
    k_compact<<<(NANC + 255) / 256, 256>>>();

    cudaFuncSetAttribute(k_sort, cudaFuncAttributeMaxDynamicSharedMemorySize, 65536);
    k_sort<<<1, 1024, 65536>>>(out);

    k_mask<<<dim3(NW, NW), 64>>>();
    k_reduce<<<1, 32>>>();
    k_final<<<(NPRE + 255) / 256, 256>>>(out);
}

// round 12
// speedup vs baseline: 1.5206x; 1.1460x over previous
#include <cuda_runtime.h>
#include <stdint.h>
#include <math.h>

typedef unsigned int u32;
typedef unsigned long long u64;

#define HH 100
#define WWID 152
#define P_TOT 15200
#define NANC 136800
#define NPRE 6000
#define NPOST 300
#define NW 94            // ceil(6000/64)
#define LOC_OFF 0
#define SCORE_OFF 547200
#define ROIS_OFF 820800
#define FS_NEGINF 0x007FFFFFu

// ------------------- scratch (static device globals: no allocation) ---------
__device__ float g_h[512 * P_TOT];          // conv1 output, [oc][p]
__device__ float g_roi[NANC * 4];           // clipped boxes per anchor
__device__ u64   g_keys[NANC];              // (flipped score)<<32 | ~index
__device__ int   g_hist[1024];              // 4 levels x 256 bins
__device__ u32   g_prefix;
__device__ int   g_count_gt;
__device__ int   g_ccount;
__device__ u64   g_cand[8192];
__device__ float g_sboxes[NPRE * 4];        // top-6000 boxes, score order
__device__ unsigned char g_svalid[NPRE + 64];
__device__ u64   g_mask[(size_t)NPRE * NW]; // NMS suppression bitmatrix
__device__ u64   g_keep[NW];
__device__ int   g_keeppre[NW];

// ========================= tf32 helpers (mma.sync path) ======================
__device__ __forceinline__ void split_tf32(float a, uint32_t& hi, uint32_t& lo) {
    uint32_t h;
    asm("cvt.rna.tf32.f32 %0, %1;" : "=r"(h) : "f"(a));
    float l = a - __uint_as_float(h);
    uint32_t lb;
    asm("cvt.rna.tf32.f32 %0, %1;" : "=r"(lb) : "f"(l));
    hi = h; lo = lb;
}

__device__ __forceinline__ void mma8(float* c, const uint32_t* a, const uint32_t* b) {
    asm volatile(
        "mma.sync.aligned.m16n8k8.row.col.f32.tf32.tf32.f32 "
        "{%0,%1,%2,%3},{%4,%5,%6,%7},{%8,%9},{%0,%1,%2,%3};"
        : "+f"(c[0]), "+f"(c[1]), "+f"(c[2]), "+f"(c[3])
        : "r"(a[0]), "r"(a[1]), "r"(a[2]), "r"(a[3]), "r"(b[0]), "r"(b[1]));
}

// SMEM (floats): A_frag hi/lo: [8 m_tiles * 4 ksteps][32 lanes][4 regs] = 4096 each
//                B_frag hi/lo: [16 n_tiles * 4 ksteps][32 lanes][2 regs] = 4096 each
#define SM_AHI 0
#define SM_ALO 4096
#define SM_BHI 8192
#define SM_BLO 12288
#define SM_FLOATS 16384
#define NCHUNK 144              // 4608 / 32

// ------------- conv 3x3 via mma.sync tf32x3 + windowed accumulation ----------
// In-tensor-core C accumulation is limited to a 2-chunk window (bounds the
// TC internal-rounding chain); windows are summed in fp32 FFMA registers.
__global__ void __launch_bounds__(256, 1)
k_conv_mma(const float* __restrict__ x, const float* __restrict__ w,
           const float* __restrict__ bias) {
    extern __shared__ float sm[];
    float* a_hi = sm + SM_AHI;
    float* a_lo = sm + SM_ALO;
    float* b_hi = sm + SM_BHI;
    float* b_lo = sm + SM_BLO;

    const int t = threadIdx.x;
    const int wid = t >> 5;
    const int lane = t & 31;
    const int p0  = blockIdx.x * 128;
    const int oc0 = blockIdx.y * 128;
    const int warp_m = wid >> 2;   // 0..1 (64 oc each)
    const int warp_n = wid & 3;    // 0..3 (32 p each)

    float macc[4][4][4];   // master accumulator (fp32 adds)
    float cacc[4][4][4];   // per-window tensor-core accumulator
#pragma unroll
    for (int i = 0; i < 4; i++)
#pragma unroll
        for (int j = 0; j < 4; j++)
#pragma unroll
            for (int r = 0; r < 4; r++) { macc[i][j][r] = 0.f; cacc[i][j][r] = 0.f; }

    // A loader: thread handles row = t>>1, 16 cols starting at (t&1)*16
    const int arow  = t >> 1;
    const int acol0 = (t & 1) * 16;
    // B loader: thread handles col kk = t>>3 for 16 p starting at (t&7)*16
    const int kk   = t >> 3;
    const int pseg = (t & 7) * 16;

    for (int ch = 0; ch < NCHUNK; ch++) {
        const int k0 = ch * 32;
        // ---- A: weights [128 oc x 32 k] -> fragment-permuted hi/lo ---------
        {
            const float* wr = w + (size_t)(oc0 + arow) * 4608 + k0 + acol0;
            const int m_tile = arow >> 4;
            const int rr = arow & 15;
            const int rbit = rr >> 3;
#pragma unroll
            for (int q = 0; q < 4; q++) {
                float4 v = *(const float4*)(wr + q * 4);
                float vv[4] = {v.x, v.y, v.z, v.w};
#pragma unroll
                for (int e = 0; e < 4; e++) {
                    int col = acol0 + q * 4 + e;
                    uint32_t hi, lo;
                    split_tf32(vv[e], hi, lo);
                    int kstep = col >> 3;
                    int kc = col & 7;
                    int ln = ((rr & 7) << 2) | (kc & 3);
                    int rg = rbit | ((kc >> 2) << 1);
                    int off = (((m_tile * 4 + kstep) * 32) + ln) * 4 + rg;
                    a_hi[off] = __uint_as_float(hi);
                    a_lo[off] = __uint_as_float(lo);
                }
            }
        }
        // ---- B: im2col [128 p x 32 k] -> fragment-permuted hi/lo -----------
        {
            int k = k0 + kk;
            int ic = k / 9;
            int r = k - ic * 9;
            int dy = r / 3 - 1;
            int dx = r - (r / 3) * 3 - 1;
            const float* xr = x + (size_t)ic * P_TOT;
            const int kstep = kk >> 3;
            const int kc = kk & 7;
            const int rg = kc >> 2;
#pragma unroll 4
            for (int j = 0; j < 16; j++) {
                int pl = pseg + j;
                int pg = p0 + pl;
                int y = pg / WWID;
                int xx = pg - y * WWID;
                int yy = y + dy;
                int x2 = xx + dx;
                float v = 0.f;
                if (pg < P_TOT && (unsigned)yy < HH && (unsigned)x2 < WWID)
                    v = __ldg(xr + yy * WWID + x2);
                uint32_t hi, lo;
                split_tf32(v, hi, lo);
                int n_tile = pl >> 3;
                int nn = pl & 7;
                int ln = (nn << 2) | (kc & 3);
                int off = (((n_tile * 4 + kstep) * 32) + ln) * 2 + rg;
                b_hi[off] = __uint_as_float(hi);
                b_lo[off] = __uint_as_float(lo);
            }
        }
        __syncthreads();
        // ---- compute: 4 k-steps, 3 passes (hi*hi, hi*lo, lo*hi) ------------
#pragma unroll
        for (int ks = 0; ks < 4; ks++) {
            uint32_t Ah[4][4], Al[4][4], Bh[4][2], Bl[4][2];
#pragma unroll
            for (int i = 0; i < 4; i++) {
                int m_tile = warp_m * 4 + i;
                int base = (((m_tile * 4 + ks) * 32) + lane) * 4;
                float4 vh = *(const float4*)(a_hi + base);
                float4 vl = *(const float4*)(a_lo + base);
                Ah[i][0] = __float_as_uint(vh.x); Ah[i][1] = __float_as_uint(vh.y);
                Ah[i][2] = __float_as_uint(vh.z); Ah[i][3] = __float_as_uint(vh.w);
                Al[i][0] = __float_as_uint(vl.x); Al[i][1] = __float_as_uint(vl.y);
                Al[i][2] = __float_as_uint(vl.z); Al[i][3] = __float_as_uint(vl.w);
            }
#pragma unroll
            for (int j = 0; j < 4; j++) {
                int n_tile = warp_n * 4 + j;
                int base = (((n_tile * 4 + ks) * 32) + lane) * 2;
                float2 vh = *(const float2*)(b_hi + base);
                float2 vl = *(const float2*)(b_lo + base);
                Bh[j][0] = __float_as_uint(vh.x); Bh[j][1] = __float_as_uint(vh.y);
                Bl[j][0] = __float_as_uint(vl.x); Bl[j][1] = __float_as_uint(vl.y);
            }
#pragma unroll
            for (int i = 0; i < 4; i++)
#pragma unroll
                for (int j = 0; j < 4; j++) mma8(cacc[i][j], Ah[i], Bh[j]);
#pragma unroll
            for (int i = 0; i < 4; i++)
#pragma unroll
                for (int j = 0; j < 4; j++) mma8(cacc[i][j], Ah[i], Bl[j]);
#pragma unroll
            for (int i = 0; i < 4; i++)
#pragma unroll
                for (int j = 0; j < 4; j++) mma8(cacc[i][j], Al[i], Bh[j]);
        }
        __syncthreads();
        // ---- window flush (every 2 chunks): drain TC acc into fp32 master --
        if (ch & 1) {
#pragma unroll
            for (int i = 0; i < 4; i++)
#pragma unroll
                for (int j = 0; j < 4; j++)
#pragma unroll
                    for (int r = 0; r < 4; r++) {
                        macc[i][j][r] += cacc[i][j][r];
                        cacc[i][j][r] = 0.f;
                    }
        }
    }
    // ---- epilogue: bias + relu, write g_h[oc][p] ----------------------------
#pragma unroll
    for (int i = 0; i < 4; i++) {
        int m_tile = warp_m * 4 + i;
        int r0 = oc0 + m_tile * 16 + (lane >> 2);
        float bb0 = __ldg(bias + r0);
        float bb1 = __ldg(bias + r0 + 8);
        float* gp0 = g_h + (size_t)r0 * P_TOT;
        float* gp1 = g_h + (size_t)(r0 + 8) * P_TOT;
#pragma unroll
        for (int j = 0; j < 4; j++) {
            int n_tile = warp_n * 4 + j;
            int c0 = p0 + n_tile * 8 + 2 * (lane & 3);
            if (c0 < P_TOT) {
                float2 v0, v1;
                v0.x = fmaxf(macc[i][j][0] + bb0, 0.f);
                v0.y = fmaxf(macc[i][j][1] + bb0, 0.f);
                v1.x = fmaxf(macc[i][j][2] + bb1, 0.f);
                v1.y = fmaxf(macc[i][j][3] + bb1, 0.f);
                *(float2*)(gp0 + c0) = v0;
                *(float2*)(gp1 + c0) = v1;
            }
        }
    }
}

// ------------------------------- heads (1x1 convs) ---------------------------
__global__ void k_heads(const float* __restrict__ sw, const float* __restrict__ sb,
                        const float* __restrict__ lw, const float* __restrict__ lb,
                        float* __restrict__ out) {
    __shared__ float hs[16][68];   // [p_local][c_chunk]
    __shared__ float ws[54][68];   // [ch][c_chunk]
    const int p0 = blockIdx.x * 16;
    const int t  = threadIdx.x;    // 864 threads
    const int pl = t & 15;
    const int ch = t >> 4;         // 0..53
    float acc = 0.f;

    for (int c0 = 0; c0 < 512; c0 += 64) {
        for (int e = t; e < 54 * 64; e += 864) {
            int cc  = e & 63;
            int chh = e >> 6;
            float v = (chh < 18) ? sw[chh * 512 + c0 + cc]
                                 : lw[(chh - 18) * 512 + c0 + cc];
            ws[chh][cc] = v;
        }
        for (int e = t; e < 16 * 64; e += 864) {
            int pp = e & 15;
            int cc = e >> 4;
            hs[pp][cc] = g_h[(size_t)(c0 + cc) * P_TOT + p0 + pp];
        }
        __syncthreads();
#pragma unroll
        for (int c4 = 0; c4 < 64; c4 += 4) {
            float4 wv = *(const float4*)&ws[ch][c4];
            float4 hv = *(const float4*)&hs[pl][c4];
            acc += wv.x * hv.x + wv.y * hv.y + wv.z * hv.z + wv.w * hv.w;
        }
        __syncthreads();
    }
    int pg = p0 + pl;   // always < 15200 (950*16 = 15200)
    if (ch < 18) {
        acc += sb[ch];
        int anc = ch >> 1, d = ch & 1;
        out[SCORE_OFF + ((size_t)pg * 9 + anc) * 2 + d] = acc;
    } else {
        int lc = ch - 18;
        acc += lb[lc];
        int anc = lc >> 2, d = lc & 3;
        out[LOC_OFF + ((size_t)pg * 9 + anc) * 4 + d] = acc;
    }
}

// ------------------------------- proposals -----------------------------------
__device__ __forceinline__ float scal_to_f(const int* p) {
    int v = *p;
    if (v > 0 && v < 10000000) return (float)v;   // int32 scalar
    return __int_as_float(v);                     // float32 scalar fallback
}

__global__ void k_prop(const float* __restrict__ out, const int* ihp, const int* iwp) {
    int a = blockIdx.x * 256 + threadIdx.x;
    if (a >= NANC) return;
    float imh = scal_to_f(ihp);
    float imw = scal_to_f(iwp);

    int t  = a % 9;
    int p  = a / 9;
    int y  = p / WWID;
    int xi = p - y * WWID;
    int ri = t / 3, si = t - ri * 3;
    double r = (ri == 0) ? 0.5 : (ri == 1 ? 1.0 : 2.0);
    double s = (si == 0) ? 8.0 : (si == 1 ? 16.0 : 32.0);
    double hbd = 16.0 * s * sqrt(r);
    double wbd = 16.0 * s * sqrt(1.0 / r);
    float ay1 = (float)y * 16.f + (float)(8.0 - hbd / 2.0);
    float ax1 = (float)xi * 16.f + (float)(8.0 - wbd / 2.0);
    float ay2 = (float)y * 16.f + (float)(8.0 + hbd / 2.0);
    float ax2 = (float)xi * 16.f + (float)(8.0 + wbd / 2.0);

    float dy = out[LOC_OFF + (size_t)a * 4 + 0];
    float dx = out[LOC_OFF + (size_t)a * 4 + 1];
    float dh = out[LOC_OFF + (size_t)a * 4 + 2];
    float dw = out[LOC_OFF + (size_t)a * 4 + 3];

    float ah = ay2 - ay1, aw = ax2 - ax1;
    float cy = ay1 + 0.5f * ah, cx = ax1 + 0.5f * aw;
    float cy2 = dy * ah + cy, cx2 = dx * aw + cx;
    float h2 = expf(dh) * ah, w2 = expf(dw) * aw;
    float r0 = cy2 - 0.5f * h2, r1 = cx2 - 0.5f * w2;
    float r2 = cy2 + 0.5f * h2, r3 = cx2 + 0.5f * w2;
    r0 = fminf(fmaxf(r0, 0.f), imh);
    r1 = fminf(fmaxf(r1, 0.f), imw);
    r2 = fminf(fmaxf(r2, 0.f), imh);
    r3 = fminf(fmaxf(r3, 0.f), imw);
    bool valid = (r2 - r0 >= 16.f) && (r3 - r1 >= 16.f);

    float s0 = out[SCORE_OFF + (size_t)a * 2 + 0];
    float s1 = out[SCORE_OFF + (size_t)a * 2 + 1];
    float m = fmaxf(s0, s1);
    float e0 = expf(s0 - m), e1 = expf(s1 - m);
    float fg = e1 / (e0 + e1);
    float sc = valid ? fg : __int_as_float(0xff800000);

    u32 bits = __float_as_uint(sc);
    u32 fs = bits ^ ((bits & 0x80000000u) ? 0xFFFFFFFFu : 0x80000000u);
    g_keys[a] = ((u64)fs << 32) | (u32)(~(u32)a);
    g_roi[(size_t)a * 4 + 0] = r0;
    g_roi[(size_t)a * 4 + 1] = r1;
    g_roi[(size_t)a * 4 + 2] = r2;
    g_roi[(size_t)a * 4 + 3] = r3;
}

// --------------------- top-6000 selection (radix select) ---------------------
__global__ void k_clear() {
    int t = threadIdx.x;
    if (t < 1024) g_hist[t] = 0;
    if (t == 0) { g_prefix = 0u; g_count_gt = 0; g_ccount = 0; }
}

__global__ void k_hist(int L) {
    __shared__ int sh[256];
    int t = threadIdx.x;
    sh[t] = 0;
    __syncthreads();
    int idx = blockIdx.x * 256 + t;
    if (idx < NANC) {
        u32 fs = (u32)(g_keys[idx] >> 32);
        bool ok = true;
        if (L > 0) {
            int shf = 32 - 8 * L;
            ok = (fs >> shf) == (g_prefix >> shf);
        }
        if (ok) atomicAdd(&sh[(fs >> (24 - 8 * L)) & 255], 1);
    }
    __syncthreads();
    if (sh[t]) atomicAdd(&g_hist[L * 256 + t], sh[t]);
}

__global__ void k_scan(int L) {
    int need = NPRE - g_count_gt;
    int above = 0;
    int chosen = 0;
    for (int b = 255; b >= 0; b--) {
        int c = g_hist[L * 256 + b];
        if (above + c >= need) { chosen = b; break; }
        above += c;
    }
    g_prefix |= (u32)chosen << (24 - 8 * L);
    g_count_gt += above;
}

__global__ void k_compact() {
    int idx = blockIdx.x * 256 + threadIdx.x;
    if (idx >= NANC) return;
    u64 key = g_keys[idx];
    u32 fs = (u32)(key >> 32);
    if (fs >= g_prefix) {
        int pos = atomicAdd(&g_ccount, 1);
        if (pos < 8192) g_cand[pos] = key;
    }
}

// One-block bitonic sort (descending) of <=8192 candidate keys.
__global__ void k_sort(float* __restrict__ out) {
    extern __shared__ u64 sk[];
    int t = threadIdx.x;   // 1024
    int C = g_ccount;
    if (C > 8192) C = 8192;
    for (int i = t; i < 8192; i += 1024) sk[i] = (i < C) ? g_cand[i] : 0ULL;
    __syncthreads();
    for (int k = 2; k <= 8192; k <<= 1) {
        for (int j = k >> 1; j > 0; j >>= 1) {
            for (int i = t; i < 8192; i += 1024) {
                int ixj = i ^ j;
                if (ixj > i) {
                    u64 a = sk[i], b = sk[ixj];
                    bool descBlock = ((i & k) == 0);
                    bool sw = descBlock ? (a < b) : (a > b);
                    if (sw) { sk[i] = b; sk[ixj] = a; }
                }
            }
            __syncthreads();
        }
    }
    for (int i = t; i < NPRE; i += 1024) {
        u64 key = sk[i];
        u32 fs = (u32)(key >> 32);
        u32 idx = ~(u32)key;
        float b0 = 0.f, b1 = 0.f, b2 = 0.f, b3 = 0.f;
        if (key != 0ULL && idx < NANC) {
            b0 = g_roi[(size_t)idx * 4 + 0];
            b1 = g_roi[(size_t)idx * 4 + 1];
            b2 = g_roi[(size_t)idx * 4 + 2];
            b3 = g_roi[(size_t)idx * 4 + 3];
        }
        g_sboxes[i * 4 + 0] = b0;
        g_sboxes[i * 4 + 1] = b1;
        g_sboxes[i * 4 + 2] = b2;
        g_sboxes[i * 4 + 3] = b3;
        g_svalid[i] = (fs > FS_NEGINF) ? 1 : 0;
    }
    // zero the rois output region (written sparsely by k_final)
    for (int i = t; i < NPOST * 4; i += 1024) out[ROIS_OFF + i] = 0.f;
}

// ------------------------------- NMS -----------------------------------------
__global__ void k_mask() {
    __shared__ float cy1[64], cx1[64], cy2s[64], cx2s[64], car[64];
    int t = threadIdx.x;
    int bi = blockIdx.y, bj = blockIdx.x;
    int j = bj * 64 + t;
    float jy1 = 0, jx1 = 0, jy2 = 0, jx2 = 0;
    if (j < NPRE) {
        jy1 = g_sboxes[j * 4 + 0];
        jx1 = g_sboxes[j * 4 + 1];
        jy2 = g_sboxes[j * 4 + 2];
        jx2 = g_sboxes[j * 4 + 3];
    }
    cy1[t] = jy1; cx1[t] = jx1; cy2s[t] = jy2; cx2s[t] = jx2;
    car[t] = (jy2 - jy1) * (jx2 - jx1);
    __syncthreads();
    int i = bi * 64 + t;
    if (i >= NPRE) return;
    float iy1 = g_sboxes[i * 4 + 0];
    float ix1 = g_sboxes[i * 4 + 1];
    float iy2 = g_sboxes[i * 4 + 2];
    float ix2 = g_sboxes[i * 4 + 3];
    float ar = (iy2 - iy1) * (ix2 - ix1);
    u64 word = 0;
#pragma unroll 8
    for (int jj = 0; jj < 64; jj++) {
        int jg = bj * 64 + jj;
        float ih = fmaxf(fminf(iy2, cy2s[jj]) - fmaxf(iy1, cy1[jj]), 0.f);
        float iw = fmaxf(fminf(ix2, cx2s[jj]) - fmaxf(ix1, cx1[jj]), 0.f);
        float inter = ih * iw;
        float iou = inter / (ar + car[jj] - inter + 1e-9f);
        if (jg > i && jg < NPRE && iou > 0.7f) word |= 1ULL << jj;
    }
    g_mask[(size_t)i * NW + bj] = word;
}

__device__ __forceinline__ u64 apply_valid(int w, u64 k) {
    int base = w * 64;
#pragma unroll 4
    for (int b = 0; b < 64; b++) {
        int row = base + b;
        if (row >= NPRE || !g_svalid[row]) k &= ~(1ULL << b);
    }
    return k;
}

// Sequential NMS reduce with early exit at 300 valid keeps. Rows beyond the
// stopping point can only be spuriously kept; their output position is then
// >= 300 and k_final discards them.
__global__ void k_reduce() {
    int l = threadIdx.x;   // 32 lanes; lane owns words l, l+32, l+64
    u64 k0 = ~0ULL;
    u64 k1 = ~0ULL;
    u64 k2;
    {
        int w = l + 64;
        if (w < 93) k2 = ~0ULL;
        else if (w == 93) k2 = 0x0000FFFFFFFFFFFFULL;  // rows 5952..5999
        else k2 = 0ULL;
    }
    int cnt = 0;
    for (int i = 0; i < NPRE; i++) {
        int w = i >> 6;
        int slot = w >> 5;
        int src = w & 31;
        u64 kv = (slot == 0) ? k0 : ((slot == 1) ? k1 : k2);
        u64 kw = __shfl_sync(0xffffffffu, kv, src);
        if ((kw >> (i & 63)) & 1ULL) {
            const u64* mr = g_mask + (size_t)i * NW;
            u64 m0 = mr[l];
            u64 m1 = mr[l + 32];
            u64 m2 = (l + 64 < NW) ? mr[l + 64] : 0ULL;
            k0 &= ~m0;
            k1 &= ~m1;
            k2 &= ~m2;
            if (g_svalid[i]) cnt++;        // uniform across lanes
            if (cnt >= NPOST) break;
        }
    }
    g_keep[l]      = apply_valid(l, k0);
    g_keep[l + 32] = apply_valid(l + 32, k1);
    if (l + 64 < NW) g_keep[l + 64] = apply_valid(l + 64, k2);
    __syncwarp();
    if (l == 0) {
        int run = 0;
        for (int w = 0; w < NW; w++) {
            g_keeppre[w] = run;
            run += __popcll(g_keep[w]);
        }
    }
}

__global__ void k_final(float* __restrict__ out) {
    int i = blockIdx.x * 256 + threadIdx.x;
    if (i >= NPRE) return;
    int w = i >> 6, b = i & 63;
    u64 kw = g_keep[w];
    if (!((kw >> b) & 1ULL)) return;
    u64 below = kw & ((1ULL << b) - 1ULL);
    int pos = g_keeppre[w] + __popcll(below);
    if (pos < NPOST) {
        out[ROIS_OFF + pos * 4 + 0] = g_sboxes[i * 4 + 0];
        out[ROIS_OFF + pos * 4 + 1] = g_sboxes[i * 4 + 1];
        out[ROIS_OFF + pos * 4 + 2] = g_sboxes[i * 4 + 2];
        out[ROIS_OFF + pos * 4 + 3] = g_sboxes[i * 4 + 3];
    }
}

// ------------------------------- launch --------------------------------------
extern "C" void kernel_launch(void* const* d_in, const int* in_sizes, int n_in,
                              void* d_out, int out_size) {
    const float* x  = (const float*)d_in[0];
    const float* w1 = (const float*)d_in[1];
    const float* b1 = (const float*)d_in[2];
    const float* sw = (const float*)d_in[3];
    const float* sb = (const float*)d_in[4];
    const float* lw = (const float*)d_in[5];
    const float* lb = (const float*)d_in[6];
    const int* ihp  = (const int*)d_in[7];
    const int* iwp  = (const int*)d_in[8];
    float* out = (float*)d_out;

    cudaFuncSetAttribute(k_conv_mma, cudaFuncAttributeMaxDynamicSharedMemorySize,
                         SM_FLOATS * 4);
    k_conv_mma<<<dim3(119, 4), 256, SM_FLOATS * 4>>>(x, w1, b1);
    k_heads<<<950, 864>>>(sw, sb, lw, lb, out);
    k_prop<<<(NANC + 255) / 256, 256>>>(out, ihp, iwp);

    k_clear<<<1, 1024>>>();
    for (int L = 0; L < 4; L++) {
        k_hist<<<(NANC + 255) / 256, 256>>>(L);
        k_scan<<<1, 1>>>(L);
    }
    k_compact<<<(NANC + 255) / 256, 256>>>();

    cudaFuncSetAttribute(k_sort, cudaFuncAttributeMaxDynamicSharedMemorySize, 65536);
    k_sort<<<1, 1024, 65536>>>(out);

    k_mask<<<dim3(NW, NW), 64>>>();
    k_reduce<<<1, 32>>>();
    k_final<<<(NPRE + 255) / 256, 256>>>(out);
}

// round 15
// speedup vs baseline: 2.1451x; 1.4107x over previous
#include <cuda_runtime.h>
#include <stdint.h>
#include <math.h>

typedef unsigned int u32;
typedef unsigned long long u64;

#define HH 100
#define WWID 152
#define P_TOT 15200
#define NANC 136800
#define NPRE 6000
#define NPOST 300
#define NW 94            // ceil(6000/64)
#define LOC_OFF 0
#define SCORE_OFF 547200
#define ROIS_OFF 820800
#define FS_NEGINF 0x007FFFFFu

// ------------------- scratch (static device globals: no allocation) ---------
__device__ float g_h[512 * P_TOT];          // conv1 output, [oc][p]
__device__ float g_xhi[512 * P_TOT];        // pre-split input, tf32-hi
__device__ float g_xlo[512 * P_TOT];        // pre-split input, lo residual
__device__ float g_wfhi[4 * 144 * 4096];    // pre-split+fragment-permuted weights
__device__ float g_wflo[4 * 144 * 4096];
__device__ float g_roi[NANC * 4];           // clipped boxes per anchor
__device__ u64   g_keys[NANC];              // (flipped score)<<32 | ~index
__device__ int   g_hist[1024];              // 4 levels x 256 bins
__device__ u32   g_prefix;
__device__ int   g_count_gt;
__device__ int   g_ccount;
__device__ u64   g_cand[8192];
__device__ float g_sboxes[NPRE * 4];        // top-6000 boxes, score order
__device__ unsigned char g_svalid[NPRE + 64];
__device__ u64   g_mask[(size_t)NPRE * NW]; // NMS suppression bitmatrix
__device__ u64   g_keep[NW];
__device__ int   g_keeppre[NW];

// ========================= tf32 helpers (mma.sync path) ======================
__device__ __forceinline__ void split_tf32(float a, uint32_t& hi, uint32_t& lo) {
    uint32_t h;
    asm("cvt.rna.tf32.f32 %0, %1;" : "=r"(h) : "f"(a));
    float l = a - __uint_as_float(h);
    uint32_t lb;
    asm("cvt.rna.tf32.f32 %0, %1;" : "=r"(lb) : "f"(l));
    hi = h; lo = lb;
}

__device__ __forceinline__ void mma8(float* c, const uint32_t* a, const uint32_t* b) {
    asm volatile(
        "mma.sync.aligned.m16n8k8.row.col.f32.tf32.tf32.f32 "
        "{%0,%1,%2,%3},{%4,%5,%6,%7},{%8,%9},{%0,%1,%2,%3};"
        : "+f"(c[0]), "+f"(c[1]), "+f"(c[2]), "+f"(c[3])
        : "r"(a[0]), "r"(a[1]), "r"(a[2]), "r"(a[3]), "r"(b[0]), "r"(b[1]));
}

__device__ __forceinline__ uint32_t smem_u32(const void* p) {
    uint32_t a;
    asm("{ .reg .u64 t; cvta.to.shared.u64 t, %1; cvt.u32.u64 %0, t; }" : "=r"(a) : "l"(p));
    return a;
}
__device__ __forceinline__ void cpa16(uint32_t dst, const void* src) {
    asm volatile("cp.async.ca.shared.global [%0], [%1], 16;" :: "r"(dst), "l"(src));
}
__device__ __forceinline__ void cpa4(uint32_t dst, const void* src, int srcsize) {
    asm volatile("cp.async.ca.shared.global [%0], [%1], 4, %2;"
                 :: "r"(dst), "l"(src), "r"(srcsize));
}
#define CPA_COMMIT() asm volatile("cp.async.commit_group;" ::: "memory")
#define CPA_WAIT1()  asm volatile("cp.async.wait_group 1;" ::: "memory")

// stage byte layout: AHI 0, ALO 16384, BHI 32768, BLO 49152; stage = 64KB
#define STG_BYTES 65536
#define STG_FLOATS 16384
#define NCHUNK 144              // 4608 / 32

// --------------------- weight pre-split + fragment permute -------------------
// Produces, per (ocb, chunk), the full 4096-float fragment-ordered A tile
// (128 oc x 32 k): off = (((m_tile*4+kstep)*32)+lane)*4+reg, m_tile 0..7.
__global__ void k_split_w(const float* __restrict__ w) {
    int ch  = blockIdx.x;          // 0..143
    int ocb = blockIdx.y;          // 0..3
#pragma unroll
    for (int s = 0; s < 4; s++) {
        int e0 = (threadIdx.x + s * 256) * 4;   // 0..4092
        float hi4[4], lo4[4];
#pragma unroll
        for (int r = 0; r < 4; r++) {
            int e  = e0 + r;
            int rg = e & 3;
            int ln = (e >> 2) & 31;
            int g  = e >> 7;          // 0..31
            int m_tile = g >> 2;      // 0..7
            int kstep  = g & 3;
            int ocl = m_tile * 16 + (rg & 1) * 8 + (ln >> 2);
            int kin = kstep * 8 + ((rg >> 1) & 1) * 4 + (ln & 3);
            float v = w[(size_t)(ocb * 128 + ocl) * 4608 + ch * 32 + kin];
            uint32_t h, l;
            split_tf32(v, h, l);
            hi4[r] = __uint_as_float(h);
            lo4[r] = __uint_as_float(l);
        }
        size_t base = ((size_t)ocb * 144 + ch) * 4096 + e0;
        *(float4*)(g_wfhi + base) = make_float4(hi4[0], hi4[1], hi4[2], hi4[3]);
        *(float4*)(g_wflo + base) = make_float4(lo4[0], lo4[1], lo4[2], lo4[3]);
    }
}

// --------------------------- input pre-split ---------------------------------
__global__ void k_split_x(const float* __restrict__ x) {
    size_t i4 = ((size_t)blockIdx.x * 256 + threadIdx.x) * 4;
    float4 v = *(const float4*)(x + i4);
    float vv[4] = {v.x, v.y, v.z, v.w};
    float hi4[4], lo4[4];
#pragma unroll
    for (int r = 0; r < 4; r++) {
        uint32_t h, l;
        split_tf32(vv[r], h, l);
        hi4[r] = __uint_as_float(h);
        lo4[r] = __uint_as_float(l);
    }
    *(float4*)(g_xhi + i4) = make_float4(hi4[0], hi4[1], hi4[2], hi4[3]);
    *(float4*)(g_xlo + i4) = make_float4(lo4[0], lo4[1], lo4[2], lo4[3]);
}

// ---- conv 3x3: mma.sync tf32x3, windowed accumulation, cp.async 2-stage -----
__global__ void __launch_bounds__(256, 1)
k_conv_mma(const float* __restrict__ bias) {
    extern __shared__ float sm[];
    const uint32_t sbase = smem_u32(sm);

    const int t = threadIdx.x;
    const int wid = t >> 5;
    const int lane = t & 31;
    const int p0  = blockIdx.x * 128;
    const int ocb = blockIdx.y;
    const int oc0 = ocb * 128;
    const int warp_m = wid >> 2;   // 0..1 (64 oc each)
    const int warp_n = wid & 3;    // 0..3 (32 p each)

    float macc[4][4][4];
    float cacc[4][4][4];
#pragma unroll
    for (int i = 0; i < 4; i++)
#pragma unroll
        for (int j = 0; j < 4; j++)
#pragma unroll
            for (int r = 0; r < 4; r++) { macc[i][j][r] = 0.f; cacc[i][j][r] = 0.f; }

    // B loader geometry: kk = t>>3 (k within chunk), pl = (t&7) + 8j
    const int kk = t >> 3;
    const int kc = kk & 7;
    const int kstep = kk >> 3;
    const int rg = kc >> 2;
    const int plow = t & 7;

    // chunk-invariant B dst byte offsets (16 of them)
    int bdst[16];
#pragma unroll
    for (int j = 0; j < 16; j++) {
        int pl = plow + j * 8;
        int n_tile = pl >> 3;
        int nn = pl & 7;
        int ln = (nn << 2) | (kc & 3);
        bdst[j] = ((((n_tile * 4 + kstep) * 32) + ln) * 2 + rg) * 4;
    }

#define PREFETCH(CH, STG_OFF) do {                                             \
        const int _ch = (CH);                                                  \
        const uint32_t _stg = sbase + (STG_OFF);                               \
        size_t _ab = ((size_t)ocb * 144 + _ch) * 4096 + t * 16;                \
        _Pragma("unroll")                                                      \
        for (int _q = 0; _q < 4; _q++) {                                       \
            cpa16(_stg + t * 64 + _q * 16, g_wfhi + _ab + _q * 4);             \
            cpa16(_stg + 16384 + t * 64 + _q * 16, g_wflo + _ab + _q * 4);     \
        }                                                                      \
        int _k = _ch * 32 + kk;                                                \
        int _ic = _k / 9;                                                      \
        int _r = _k - _ic * 9;                                                 \
        int _dy = _r / 3 - 1;                                                  \
        int _dx = _r - (_r / 3) * 3 - 1;                                       \
        const float* _bh = g_xhi + (size_t)_ic * P_TOT;                        \
        const float* _bl = g_xlo + (size_t)_ic * P_TOT;                        \
        _Pragma("unroll")                                                      \
        for (int _j = 0; _j < 16; _j++) {                                      \
            int _pl = plow + _j * 8;                                           \
            int _pg = p0 + _pl;                                                \
            int _y = _pg / WWID;                                               \
            int _xx = _pg - _y * WWID;                                         \
            int _yy = _y + _dy;                                                \
            int _x2 = _xx + _dx;                                               \
            bool _ok = (_pg < P_TOT) && ((unsigned)_yy < HH) && ((unsigned)_x2 < WWID); \
            int _go = _ok ? (_yy * WWID + _x2) : 0;                            \
            int _sz = _ok ? 4 : 0;                                             \
            cpa4(_stg + 32768 + bdst[_j], _bh + _go, _sz);                     \
            cpa4(_stg + 49152 + bdst[_j], _bl + _go, _sz);                     \
        }                                                                      \
    } while (0)

    PREFETCH(0, 0u);
    CPA_COMMIT();

    for (int ch = 0; ch < NCHUNK; ch++) {
        if (ch + 1 < NCHUNK) PREFETCH(ch + 1, (u32)(((ch + 1) & 1) * STG_BYTES));
        CPA_COMMIT();
        CPA_WAIT1();
        __syncthreads();

        float* base = sm + (ch & 1) * STG_FLOATS;
        float* a_hi = base;
        float* a_lo = base + 4096;
        float* b_hi = base + 8192;
        float* b_lo = base + 12288;
#pragma unroll
        for (int ks = 0; ks < 4; ks++) {
            uint32_t Ah[4][4], Al[4][4], Bh[4][2], Bl[4][2];
#pragma unroll
            for (int i = 0; i < 4; i++) {
                int m_tile = warp_m * 4 + i;
                int boff = (((m_tile * 4 + ks) * 32) + lane) * 4;
                float4 vh = *(const float4*)(a_hi + boff);
                float4 vl = *(const float4*)(a_lo + boff);
                Ah[i][0] = __float_as_uint(vh.x); Ah[i][1] = __float_as_uint(vh.y);
                Ah[i][2] = __float_as_uint(vh.z); Ah[i][3] = __float_as_uint(vh.w);
                Al[i][0] = __float_as_uint(vl.x); Al[i][1] = __float_as_uint(vl.y);
                Al[i][2] = __float_as_uint(vl.z); Al[i][3] = __float_as_uint(vl.w);
            }
#pragma unroll
            for (int j = 0; j < 4; j++) {
                int n_tile = warp_n * 4 + j;
                int boff = (((n_tile * 4 + ks) * 32) + lane) * 2;
                float2 vh = *(const float2*)(b_hi + boff);
                float2 vl = *(const float2*)(b_lo + boff);
                Bh[j][0] = __float_as_uint(vh.x); Bh[j][1] = __float_as_uint(vh.y);
                Bl[j][0] = __float_as_uint(vl.x); Bl[j][1] = __float_as_uint(vl.y);
            }
#pragma unroll
            for (int i = 0; i < 4; i++)
#pragma unroll
                for (int j = 0; j < 4; j++) mma8(cacc[i][j], Ah[i], Bh[j]);
#pragma unroll
            for (int i = 0; i < 4; i++)
#pragma unroll
                for (int j = 0; j < 4; j++) mma8(cacc[i][j], Ah[i], Bl[j]);
#pragma unroll
            for (int i = 0; i < 4; i++)
#pragma unroll
                for (int j = 0; j < 4; j++) mma8(cacc[i][j], Al[i], Bh[j]);
        }
        if (ch & 1) {
#pragma unroll
            for (int i = 0; i < 4; i++)
#pragma unroll
                for (int j = 0; j < 4; j++)
#pragma unroll
                    for (int r = 0; r < 4; r++) {
                        macc[i][j][r] += cacc[i][j][r];
                        cacc[i][j][r] = 0.f;
                    }
        }
        __syncthreads();
    }
#undef PREFETCH

    // ---- epilogue: bias + relu, write g_h[oc][p] ----------------------------
#pragma unroll
    for (int i = 0; i < 4; i++) {
        int m_tile = warp_m * 4 + i;
        int r0 = oc0 + m_tile * 16 + (lane >> 2);
        float bb0 = __ldg(bias + r0);
        float bb1 = __ldg(bias + r0 + 8);
        float* gp0 = g_h + (size_t)r0 * P_TOT;
        float* gp1 = g_h + (size_t)(r0 + 8) * P_TOT;
#pragma unroll
        for (int j = 0; j < 4; j++) {
            int n_tile = warp_n * 4 + j;
            int c0 = p0 + n_tile * 8 + 2 * (lane & 3);
            if (c0 < P_TOT) {
                float2 v0, v1;
                v0.x = fmaxf(macc[i][j][0] + bb0, 0.f);
                v0.y = fmaxf(macc[i][j][1] + bb0, 0.f);
                v1.x = fmaxf(macc[i][j][2] + bb1, 0.f);
                v1.y = fmaxf(macc[i][j][3] + bb1, 0.f);
                *(float2*)(gp0 + c0) = v0;
                *(float2*)(gp1 + c0) = v1;
            }
        }
    }
}

// ------------------------------- heads (1x1 convs) ---------------------------
__global__ void k_heads(const float* __restrict__ sw, const float* __restrict__ sb,
                        const float* __restrict__ lw, const float* __restrict__ lb,
                        float* __restrict__ out) {
    __shared__ float hs[16][68];
    __shared__ float ws[54][68];
    const int p0 = blockIdx.x * 16;
    const int t  = threadIdx.x;    // 864 threads
    const int pl = t & 15;
    const int ch = t >> 4;         // 0..53
    float acc = 0.f;

    for (int c0 = 0; c0 < 512; c0 += 64) {
        for (int e = t; e < 54 * 64; e += 864) {
            int cc  = e & 63;
            int chh = e >> 6;
            float v = (chh < 18) ? sw[chh * 512 + c0 + cc]
                                 : lw[(chh - 18) * 512 + c0 + cc];
            ws[chh][cc] = v;
        }
        for (int e = t; e < 16 * 64; e += 864) {
            int pp = e & 15;
            int cc = e >> 4;
            hs[pp][cc] = g_h[(size_t)(c0 + cc) * P_TOT + p0 + pp];
        }
        __syncthreads();
#pragma unroll
        for (int c4 = 0; c4 < 64; c4 += 4) {
            float4 wv = *(const float4*)&ws[ch][c4];
            float4 hv = *(const float4*)&hs[pl][c4];
            acc += wv.x * hv.x + wv.y * hv.y + wv.z * hv.z + wv.w * hv.w;
        }
        __syncthreads();
    }
    int pg = p0 + pl;
    if (ch < 18) {
        acc += sb[ch];
        int anc = ch >> 1, d = ch & 1;
        out[SCORE_OFF + ((size_t)pg * 9 + anc) * 2 + d] = acc;
    } else {
        int lc = ch - 18;
        acc += lb[lc];
        int anc = lc >> 2, d = lc & 3;
        out[LOC_OFF + ((size_t)pg * 9 + anc) * 4 + d] = acc;
    }
}

// ------------------------------- proposals -----------------------------------
__device__ __forceinline__ float scal_to_f(const int* p) {
    int v = *p;
    if (v > 0 && v < 10000000) return (float)v;
    return __int_as_float(v);
}

__global__ void k_prop(const float* __restrict__ out, const int* ihp, const int* iwp) {
    int a = blockIdx.x * 256 + threadIdx.x;
    if (a >= NANC) return;
    float imh = scal_to_f(ihp);
    float imw = scal_to_f(iwp);

    int t  = a % 9;
    int p  = a / 9;
    int y  = p / WWID;
    int xi = p - y * WWID;
    int ri = t / 3, si = t - ri * 3;
    double r = (ri == 0) ? 0.5 : (ri == 1 ? 1.0 : 2.0);
    double s = (si == 0) ? 8.0 : (si == 1 ? 16.0 : 32.0);
    double hbd = 16.0 * s * sqrt(r);
    double wbd = 16.0 * s * sqrt(1.0 / r);
    float ay1 = (float)y * 16.f + (float)(8.0 - hbd / 2.0);
    float ax1 = (float)xi * 16.f + (float)(8.0 - wbd / 2.0);
    float ay2 = (float)y * 16.f + (float)(8.0 + hbd / 2.0);
    float ax2 = (float)xi * 16.f + (float)(8.0 + wbd / 2.0);

    float dy = out[LOC_OFF + (size_t)a * 4 + 0];
    float dx = out[LOC_OFF + (size_t)a * 4 + 1];
    float dh = out[LOC_OFF + (size_t)a * 4 + 2];
    float dw = out[LOC_OFF + (size_t)a * 4 + 3];

    float ah = ay2 - ay1, aw = ax2 - ax1;
    float cy = ay1 + 0.5f * ah, cx = ax1 + 0.5f * aw;
    float cy2 = dy * ah + cy, cx2 = dx * aw + cx;
    float h2 = expf(dh) * ah, w2 = expf(dw) * aw;
    float r0 = cy2 - 0.5f * h2, r1 = cx2 - 0.5f * w2;
    float r2 = cy2 + 0.5f * h2, r3 = cx2 + 0.5f * w2;
    r0 = fminf(fmaxf(r0, 0.f), imh);
    r1 = fminf(fmaxf(r1, 0.f), imw);
    r2 = fminf(fmaxf(r2, 0.f), imh);
    r3 = fminf(fmaxf(r3, 0.f), imw);
    bool valid = (r2 - r0 >= 16.f) && (r3 - r1 >= 16.f);

    float s0 = out[SCORE_OFF + (size_t)a * 2 + 0];
    float s1 = out[SCORE_OFF + (size_t)a * 2 + 1];
    float m = fmaxf(s0, s1);
    float e0 = expf(s0 - m), e1 = expf(s1 - m);
    float fg = e1 / (e0 + e1);
    float sc = valid ? fg : __int_as_float(0xff800000);

    u32 bits = __float_as_uint(sc);
    u32 fs = bits ^ ((bits & 0x80000000u) ? 0xFFFFFFFFu : 0x80000000u);
    g_keys[a] = ((u64)fs << 32) | (u32)(~(u32)a);
    g_roi[(size_t)a * 4 + 0] = r0;
    g_roi[(size_t)a * 4 + 1] = r1;
    g_roi[(size_t)a * 4 + 2] = r2;
    g_roi[(size_t)a * 4 + 3] = r3;
}

// --------------------- top-6000 selection (radix select) ---------------------
__global__ void k_clear() {
    int t = threadIdx.x;
    if (t < 1024) g_hist[t] = 0;
    if (t == 0) { g_prefix = 0u; g_count_gt = 0; g_ccount = 0; }
}

__global__ void k_hist(int L) {
    __shared__ int sh[256];
    int t = threadIdx.x;
    sh[t] = 0;
    __syncthreads();
    int idx = blockIdx.x * 256 + t;
    if (idx < NANC) {
        u32 fs = (u32)(g_keys[idx] >> 32);
        bool ok = true;
        if (L > 0) {
            int shf = 32 - 8 * L;
            ok = (fs >> shf) == (g_prefix >> shf);
        }
        if (ok) atomicAdd(&sh[(fs >> (24 - 8 * L)) & 255], 1);
    }
    __syncthreads();
    if (sh[t]) atomicAdd(&g_hist[L * 256 + t], sh[t]);
}

__global__ void k_scan(int L) {
    int need = NPRE - g_count_gt;
    int above = 0;
    int chosen = 0;
    for (int b = 255; b >= 0; b--) {
        int c = g_hist[L * 256 + b];
        if (above + c >= need) { chosen = b; break; }
        above += c;
    }
    g_prefix |= (u32)chosen << (24 - 8 * L);
    g_count_gt += above;
}

__global__ void k_compact() {
    int idx = blockIdx.x * 256 + threadIdx.x;
    if (idx >= NANC) return;
    u64 key = g_keys[idx];
    u32 fs = (u32)(key >> 32);
    if (fs >= g_prefix) {
        int pos = atomicAdd(&g_ccount, 1);
        if (pos < 8192) g_cand[pos] = key;
    }
}

// One-block bitonic sort (descending) of <=8192 candidate keys.
__global__ void k_sort(float* __restrict__ out) {
    extern __shared__ u64 sk[];
    int t = threadIdx.x;   // 1024
    int C = g_ccount;
    if (C > 8192) C = 8192;
    for (int i = t; i < 8192; i += 1024) sk[i] = (i < C) ? g_cand[i] : 0ULL;
    __syncthreads();
    for (int k = 2; k <= 8192; k <<= 1) {
        for (int j = k >> 1; j > 0; j >>= 1) {
            for (int i = t; i < 8192; i += 1024) {
                int ixj = i ^ j;
                if (ixj > i) {
                    u64 a = sk[i], b = sk[ixj];
                    bool descBlock = ((i & k) == 0);
                    bool sw = descBlock ? (a < b) : (a > b);
                    if (sw) { sk[i] = b; sk[ixj] = a; }
                }
            }
            __syncthreads();
        }
    }
    for (int i = t; i < NPRE; i += 1024) {
        u64 key = sk[i];
        u32 fs = (u32)(key >> 32);
        u32 idx = ~(u32)key;
        float b0 = 0.f, b1 = 0.f, b2 = 0.f, b3 = 0.f;
        if (key != 0ULL && idx < NANC) {
            b0 = g_roi[(size_t)idx * 4 + 0];
            b1 = g_roi[(size_t)idx * 4 + 1];
            b2 = g_roi[(size_t)idx * 4 + 2];
            b3 = g_roi[(size_t)idx * 4 + 3];
        }
        g_sboxes[i * 4 + 0] = b0;
        g_sboxes[i * 4 + 1] = b1;
        g_sboxes[i * 4 + 2] = b2;
        g_sboxes[i * 4 + 3] = b3;
        g_svalid[i] = (fs > FS_NEGINF) ? 1 : 0;
    }
    for (int i = t; i < NPOST * 4; i += 1024) out[ROIS_OFF + i] = 0.f;
}

// ------------------------------- NMS -----------------------------------------
__global__ void k_mask() {
    __shared__ float cy1[64], cx1[64], cy2s[64], cx2s[64], car[64];
    int t = threadIdx.x;
    int bi = blockIdx.y, bj = blockIdx.x;
    int j = bj * 64 + t;
    float jy1 = 0, jx1 = 0, jy2 = 0, jx2 = 0;
    if (j < NPRE) {
        jy1 = g_sboxes[j * 4 + 0];
        jx1 = g_sboxes[j * 4 + 1];
        jy2 = g_sboxes[j * 4 + 2];
        jx2 = g_sboxes[j * 4 + 3];
    }
    cy1[t] = jy1; cx1[t] = jx1; cy2s[t] = jy2; cx2s[t] = jx2;
    car[t] = (jy2 - jy1) * (jx2 - jx1);
    __syncthreads();
    int i = bi * 64 + t;
    if (i >= NPRE) return;
    float iy1 = g_sboxes[i * 4 + 0];
    float ix1 = g_sboxes[i * 4 + 1];
    float iy2 = g_sboxes[i * 4 + 2];
    float ix2 = g_sboxes[i * 4 + 3];
    float ar = (iy2 - iy1) * (ix2 - ix1);
    u64 word = 0;
#pragma unroll 8
    for (int jj = 0; jj < 64; jj++) {
        int jg = bj * 64 + jj;
        float ih = fmaxf(fminf(iy2, cy2s[jj]) - fmaxf(iy1, cy1[jj]), 0.f);
        float iw = fmaxf(fminf(ix2, cx2s[jj]) - fmaxf(ix1, cx1[jj]), 0.f);
        float inter = ih * iw;
        float iou = inter / (ar + car[jj] - inter + 1e-9f);
        if (jg > i && jg < NPRE && iou > 0.7f) word |= 1ULL << jj;
    }
    g_mask[(size_t)i * NW + bj] = word;
}

__device__ __forceinline__ u64 apply_valid(int w, u64 k) {
    int base = w * 64;
#pragma unroll 4
    for (int b = 0; b < 64; b++) {
        int row = base + b;
        if (row >= NPRE || !g_svalid[row]) k &= ~(1ULL << b);
    }
    return k;
}

// Producer/consumer NMS reduce: warps 1-3 prefetch 64-row mask windows into a
// 4-slot SMEM ring; warp 0 runs the serial suppression chain from SMEM.
// Early exit at 300 valid keeps.
#define RWIN 94                  // windows of 64 rows
#define RSLOT_W (64 * NW)        // u64 words per slot
__global__ void k_reduce2() {
    extern __shared__ u64 ring[];            // 4 * RSLOT_W u64
    __shared__ volatile int prod_gen[4];
    __shared__ volatile int cons_done;
    __shared__ volatile int finished;
    int t = threadIdx.x, wid = t >> 5, l = t & 31;
    if (t < 4) prod_gen[t] = -1;
    if (t == 4) { cons_done = -1; finished = 0; }
    __syncthreads();

    if (wid > 0) {
        for (int w = wid - 1; w < RWIN; w += 3) {
            int slot = w & 3;
            while (cons_done < w - 4 && !finished) { }
            if (finished) break;
            u64* dst = ring + (size_t)slot * RSLOT_W;
            const u64* src = g_mask + (size_t)w * 64 * NW;
            int rows = min(64, NPRE - w * 64);
            int total = rows * NW;
            for (int i = l; i < total; i += 32) dst[i] = src[i];
            __threadfence_block();
            __syncwarp();
            if (l == 0) prod_gen[slot] = w;
        }
    } else {
        u64 k0 = ~0ULL;
        u64 k1 = ~0ULL;
        u64 k2;
        {
            int w = l + 64;
            if (w < 93) k2 = ~0ULL;
            else if (w == 93) k2 = 0x0000FFFFFFFFFFFFULL;
            else k2 = 0ULL;
        }
        int cnt = 0;
        bool stop = false;
        for (int w = 0; w < RWIN && !stop; w++) {
            int slot = w & 3;
            while (prod_gen[slot] != w) { }
            __threadfence_block();
            const u64* win = ring + (size_t)slot * RSLOT_W;
            int rows = min(64, NPRE - w * 64);
            for (int r = 0; r < rows; r++) {
                int i = w * 64 + r;
                int iw = i >> 6;
                int sl = iw >> 5;
                int src = iw & 31;
                u64 kv = (sl == 0) ? k0 : ((sl == 1) ? k1 : k2);
                u64 kw = __shfl_sync(0xffffffffu, kv, src);
                if ((kw >> (i & 63)) & 1ULL) {
                    const u64* mr = win + (size_t)r * NW;
                    u64 m0 = mr[l];
                    u64 m1 = mr[l + 32];
                    u64 m2 = (l + 64 < NW) ? mr[l + 64] : 0ULL;
                    k0 &= ~m0;
                    k1 &= ~m1;
                    k2 &= ~m2;
                    if (g_svalid[i]) cnt++;
                    if (cnt >= NPOST) { stop = true; break; }
                }
            }
            if (l == 0) cons_done = w;
        }
        if (l == 0) finished = 1;

        g_keep[l]      = apply_valid(l, k0);
        g_keep[l + 32] = apply_valid(l + 32, k1);
        if (l + 64 < NW) g_keep[l + 64] = apply_valid(l + 64, k2);
        __syncwarp();
        if (l == 0) {
            int run = 0;
            for (int w = 0; w < NW; w++) {
                g_keeppre[w] = run;
                run += __popcll(g_keep[w]);
            }
        }
    }
}

__global__ void k_final(float* __restrict__ out) {
    int i = blockIdx.x * 256 + threadIdx.x;
    if (i >= NPRE) return;
    int w = i >> 6, b = i & 63;
    u64 kw = g_keep[w];
    if (!((kw >> b) & 1ULL)) return;
    u64 below = kw & ((1ULL << b) - 1ULL);
    int pos = g_keeppre[w] + __popcll(below);
    if (pos < NPOST) {
        out[ROIS_OFF + pos * 4 + 0] = g_sboxes[i * 4 + 0];
        out[ROIS_OFF + pos * 4 + 1] = g_sboxes[i * 4 + 1];
        out[ROIS_OFF + pos * 4 + 2] = g_sboxes[i * 4 + 2];
        out[ROIS_OFF + pos * 4 + 3] = g_sboxes[i * 4 + 3];
    }
}

// ------------------------------- launch --------------------------------------
extern "C" void kernel_launch(void* const* d_in, const int* in_sizes, int n_in,
                              void* d_out, int out_size) {
    const float* x  = (const float*)d_in[0];
    const float* w1 = (const float*)d_in[1];
    const float* b1 = (const float*)d_in[2];
    const float* sw = (const float*)d_in[3];
    const float* sb = (const float*)d_in[4];
    const float* lw = (const float*)d_in[5];
    const float* lb = (const float*)d_in[6];
    const int* ihp  = (const int*)d_in[7];
    const int* iwp  = (const int*)d_in[8];
    float* out = (float*)d_out;

    // launch order puts k_conv_mma in the ncu capture slot (our 4th launch)
    k_clear<<<1, 1024>>>();
    k_split_w<<<dim3(144, 4), 256>>>(w1);
    k_split_x<<<7600, 256>>>(x);

    cudaFuncSetAttribute(k_conv_mma, cudaFuncAttributeMaxDynamicSharedMemorySize,
                         2 * STG_BYTES);
    k_conv_mma<<<dim3(119, 4), 256, 2 * STG_BYTES>>>(b1);

    k_heads<<<950, 864>>>(sw, sb, lw, lb, out);
    k_prop<<<(NANC + 255) / 256, 256>>>(out, ihp, iwp);

    for (int L = 0; L < 4; L++) {
        k_hist<<<(NANC + 255) / 256, 256>>>(L);
        k_scan<<<1, 1>>>(L);
    }
    k_compact<<<(NANC + 255) / 256, 256>>>();

    cudaFuncSetAttribute(k_sort, cudaFuncAttributeMaxDynamicSharedMemorySize, 65536);
    k_sort<<<1, 1024, 65536>>>(out);

    k_mask<<<dim3(NW, NW), 64>>>();

    cudaFuncSetAttribute(k_reduce2, cudaFuncAttributeMaxDynamicSharedMemorySize,
                         4 * RSLOT_W * 8);
    k_reduce2<<<1, 128, 4 * RSLOT_W * 8>>>();
    k_final<<<(NPRE + 255) / 256, 256>>>(out);
}

// round 16
// speedup vs baseline: 2.1565x; 1.0053x over previous
#include <cuda_runtime.h>
#include <stdint.h>
#include <math.h>

typedef unsigned int u32;
typedef unsigned long long u64;

#define HH 100
#define WWID 152
#define P_TOT 15200
#define NANC 136800
#define NPRE 6000
#define NPOST 300
#define NW 94            // ceil(6000/64)
#define LOC_OFF 0
#define SCORE_OFF 547200
#define ROIS_OFF 820800
#define FS_NEGINF 0x007FFFFFu

// ------------------- scratch (static device globals: no allocation) ---------
__device__ float g_h[512 * P_TOT];          // conv1 output, [oc][p]
__device__ float g_xhi[512 * P_TOT];        // pre-split input, tf32-hi
__device__ float g_xlo[512 * P_TOT];        // pre-split input, lo residual
__device__ float g_wfhi[4 * 144 * 4096];    // pre-split+fragment-permuted weights
__device__ float g_wflo[4 * 144 * 4096];
__device__ float g_roi[NANC * 4];           // clipped boxes per anchor
__device__ u64   g_keys[NANC];              // (flipped score)<<32 | ~index
__device__ int   g_hist[1024];              // 4 levels x 256 bins
__device__ u32   g_prefix;
__device__ int   g_count_gt;
__device__ int   g_ccount;
__device__ u64   g_cand[8192];
__device__ float g_sboxes[NPRE * 4];        // top-6000 boxes, score order
__device__ unsigned char g_svalid[NPRE + 64];
__device__ u64   g_mask[(size_t)NPRE * NW]; // NMS suppression bitmatrix
__device__ u64   g_keep[NW];
__device__ int   g_keeppre[NW];

// ========================= tf32 helpers (mma.sync path) ======================
__device__ __forceinline__ void split_tf32(float a, uint32_t& hi, uint32_t& lo) {
    uint32_t h;
    asm("cvt.rna.tf32.f32 %0, %1;" : "=r"(h) : "f"(a));
    float l = a - __uint_as_float(h);
    uint32_t lb;
    asm("cvt.rna.tf32.f32 %0, %1;" : "=r"(lb) : "f"(l));
    hi = h; lo = lb;
}

__device__ __forceinline__ void mma8(float* c, const uint32_t* a, const uint32_t* b) {
    asm volatile(
        "mma.sync.aligned.m16n8k8.row.col.f32.tf32.tf32.f32 "
        "{%0,%1,%2,%3},{%4,%5,%6,%7},{%8,%9},{%0,%1,%2,%3};"
        : "+f"(c[0]), "+f"(c[1]), "+f"(c[2]), "+f"(c[3])
        : "r"(a[0]), "r"(a[1]), "r"(a[2]), "r"(a[3]), "r"(b[0]), "r"(b[1]));
}

__device__ __forceinline__ uint32_t smem_u32(const void* p) {
    uint32_t a;
    asm("{ .reg .u64 t; cvta.to.shared.u64 t, %1; cvt.u32.u64 %0, t; }" : "=r"(a) : "l"(p));
    return a;
}
__device__ __forceinline__ void cpa16(uint32_t dst, const void* src) {
    asm volatile("cp.async.ca.shared.global [%0], [%1], 16;" :: "r"(dst), "l"(src));
}
__device__ __forceinline__ void cpa4(uint32_t dst, const void* src, int srcsize) {
    asm volatile("cp.async.ca.shared.global [%0], [%1], 4, %2;"
                 :: "r"(dst), "l"(src), "r"(srcsize));
}
#define CPA_COMMIT() asm volatile("cp.async.commit_group;" ::: "memory")
#define CPA_WAIT1()  asm volatile("cp.async.wait_group 1;" ::: "memory")

// stage byte layout: AHI 0, ALO 16384, BHI 32768, BLO 49152; stage = 64KB
#define STG_BYTES 65536
#define STG_FLOATS 16384
#define NCHUNK 144              // 4608 / 32

// --------------------- weight pre-split + fragment permute -------------------
// Produces, per (ocb, chunk), the full 4096-float fragment-ordered A tile
// (128 oc x 32 k): off = (((m_tile*4+kstep)*32)+lane)*4+reg, m_tile 0..7.
__global__ void k_split_w(const float* __restrict__ w) {
    int ch  = blockIdx.x;          // 0..143
    int ocb = blockIdx.y;          // 0..3
#pragma unroll
    for (int s = 0; s < 4; s++) {
        int e0 = (threadIdx.x + s * 256) * 4;   // 0..4092
        float hi4[4], lo4[4];
#pragma unroll
        for (int r = 0; r < 4; r++) {
            int e  = e0 + r;
            int rg = e & 3;
            int ln = (e >> 2) & 31;
            int g  = e >> 7;          // 0..31
            int m_tile = g >> 2;      // 0..7
            int kstep  = g & 3;
            int ocl = m_tile * 16 + (rg & 1) * 8 + (ln >> 2);
            int kin = kstep * 8 + ((rg >> 1) & 1) * 4 + (ln & 3);
            float v = w[(size_t)(ocb * 128 + ocl) * 4608 + ch * 32 + kin];
            uint32_t h, l;
            split_tf32(v, h, l);
            hi4[r] = __uint_as_float(h);
            lo4[r] = __uint_as_float(l);
        }
        size_t base = ((size_t)ocb * 144 + ch) * 4096 + e0;
        *(float4*)(g_wfhi + base) = make_float4(hi4[0], hi4[1], hi4[2], hi4[3]);
        *(float4*)(g_wflo + base) = make_float4(lo4[0], lo4[1], lo4[2], lo4[3]);
    }
}

// --------------------------- input pre-split ---------------------------------
__global__ void k_split_x(const float* __restrict__ x) {
    size_t i4 = ((size_t)blockIdx.x * 256 + threadIdx.x) * 4;
    float4 v = *(const float4*)(x + i4);
    float vv[4] = {v.x, v.y, v.z, v.w};
    float hi4[4], lo4[4];
#pragma unroll
    for (int r = 0; r < 4; r++) {
        uint32_t h, l;
        split_tf32(vv[r], h, l);
        hi4[r] = __uint_as_float(h);
        lo4[r] = __uint_as_float(l);
    }
    *(float4*)(g_xhi + i4) = make_float4(hi4[0], hi4[1], hi4[2], hi4[3]);
    *(float4*)(g_xlo + i4) = make_float4(lo4[0], lo4[1], lo4[2], lo4[3]);
}

// ---- conv 3x3: mma.sync tf32x3, windowed accum, cp.async 2-stage, 16 warps --
// 512 threads: warp grid 4(m) x 4(n); each warp owns 32oc x 32p = 2x4 mma tiles.
// Per-thread regs ~124 -> 16 warps/SM (occ 25%, 2x round-15) hide HMMA/LDS lat.
__global__ void __launch_bounds__(512, 1)
k_conv_mma(const float* __restrict__ bias) {
    extern __shared__ float sm[];
    const uint32_t sbase = smem_u32(sm);

    const int t = threadIdx.x;
    const int wid = t >> 5;
    const int lane = t & 31;
    const int p0  = blockIdx.x * 128;
    const int ocb = blockIdx.y;
    const int oc0 = ocb * 128;
    const int warp_m = wid >> 2;   // 0..3 (32 oc each)
    const int warp_n = wid & 3;    // 0..3 (32 p each)

    float macc[2][4][4];
    float cacc[2][4][4];
#pragma unroll
    for (int i = 0; i < 2; i++)
#pragma unroll
        for (int j = 0; j < 4; j++)
#pragma unroll
            for (int r = 0; r < 4; r++) { macc[i][j][r] = 0.f; cacc[i][j][r] = 0.f; }

    // B loader geometry: kk = t>>4 (k within chunk), pl = (t&15) + 16j
    const int kk = t >> 4;         // 0..31
    const int kc = kk & 7;
    const int kstep = kk >> 3;
    const int rg = kc >> 2;
    const int plow = t & 15;

    // chunk-invariant B dst byte offsets (8 of them)
    int bdst[8];
#pragma unroll
    for (int j = 0; j < 8; j++) {
        int pl = plow + j * 16;
        int n_tile = pl >> 3;
        int nn = pl & 7;
        int ln = (nn << 2) | (kc & 3);
        bdst[j] = ((((n_tile * 4 + kstep) * 32) + ln) * 2 + rg) * 4;
    }

#define PREFETCH(CH, STG_OFF) do {                                             \
        const int _ch = (CH);                                                  \
        const uint32_t _stg = sbase + (STG_OFF);                               \
        size_t _ab = ((size_t)ocb * 144 + _ch) * 4096 + t * 8;                 \
        _Pragma("unroll")                                                      \
        for (int _q = 0; _q < 2; _q++) {                                       \
            cpa16(_stg + t * 32 + _q * 16, g_wfhi + _ab + _q * 4);             \
            cpa16(_stg + 16384 + t * 32 + _q * 16, g_wflo + _ab + _q * 4);     \
        }                                                                      \
        int _k = _ch * 32 + kk;                                                \
        int _ic = _k / 9;                                                      \
        int _r = _k - _ic * 9;                                                 \
        int _dy = _r / 3 - 1;                                                  \
        int _dx = _r - (_r / 3) * 3 - 1;                                       \
        const float* _bh = g_xhi + (size_t)_ic * P_TOT;                        \
        const float* _bl = g_xlo + (size_t)_ic * P_TOT;                        \
        _Pragma("unroll")                                                      \
        for (int _j = 0; _j < 8; _j++) {                                       \
            int _pl = plow + _j * 16;                                          \
            int _pg = p0 + _pl;                                                \
            int _y = _pg / WWID;                                               \
            int _xx = _pg - _y * WWID;                                         \
            int _yy = _y + _dy;                                                \
            int _x2 = _xx + _dx;                                               \
            bool _ok = (_pg < P_TOT) && ((unsigned)_yy < HH) && ((unsigned)_x2 < WWID); \
            int _go = _ok ? (_yy * WWID + _x2) : 0;                            \
            int _sz = _ok ? 4 : 0;                                             \
            cpa4(_stg + 32768 + bdst[_j], _bh + _go, _sz);                     \
            cpa4(_stg + 49152 + bdst[_j], _bl + _go, _sz);                     \
        }                                                                      \
    } while (0)

    PREFETCH(0, 0u);
    CPA_COMMIT();

    for (int ch = 0; ch < NCHUNK; ch++) {
        if (ch + 1 < NCHUNK) PREFETCH(ch + 1, (u32)(((ch + 1) & 1) * STG_BYTES));
        CPA_COMMIT();
        CPA_WAIT1();
        __syncthreads();

        float* base = sm + (ch & 1) * STG_FLOATS;
        float* a_hi = base;
        float* a_lo = base + 4096;
        float* b_hi = base + 8192;
        float* b_lo = base + 12288;
#pragma unroll
        for (int ks = 0; ks < 4; ks++) {
            uint32_t Ah[2][4], Al[2][4], Bh[4][2], Bl[4][2];
#pragma unroll
            for (int i = 0; i < 2; i++) {
                int m_tile = warp_m * 2 + i;
                int boff = (((m_tile * 4 + ks) * 32) + lane) * 4;
                float4 vh = *(const float4*)(a_hi + boff);
                float4 vl = *(const float4*)(a_lo + boff);
                Ah[i][0] = __float_as_uint(vh.x); Ah[i][1] = __float_as_uint(vh.y);
                Ah[i][2] = __float_as_uint(vh.z); Ah[i][3] = __float_as_uint(vh.w);
                Al[i][0] = __float_as_uint(vl.x); Al[i][1] = __float_as_uint(vl.y);
                Al[i][2] = __float_as_uint(vl.z); Al[i][3] = __float_as_uint(vl.w);
            }
#pragma unroll
            for (int j = 0; j < 4; j++) {
                int n_tile = warp_n * 4 + j;
                int boff = (((n_tile * 4 + ks) * 32) + lane) * 2;
                float2 vh = *(const float2*)(b_hi + boff);
                float2 vl = *(const float2*)(b_lo + boff);
                Bh[j][0] = __float_as_uint(vh.x); Bh[j][1] = __float_as_uint(vh.y);
                Bl[j][0] = __float_as_uint(vl.x); Bl[j][1] = __float_as_uint(vl.y);
            }
#pragma unroll
            for (int i = 0; i < 2; i++)
#pragma unroll
                for (int j = 0; j < 4; j++) mma8(cacc[i][j], Ah[i], Bh[j]);
#pragma unroll
            for (int i = 0; i < 2; i++)
#pragma unroll
                for (int j = 0; j < 4; j++) mma8(cacc[i][j], Ah[i], Bl[j]);
#pragma unroll
            for (int i = 0; i < 2; i++)
#pragma unroll
                for (int j = 0; j < 4; j++) mma8(cacc[i][j], Al[i], Bh[j]);
        }
        if (ch & 1) {
#pragma unroll
            for (int i = 0; i < 2; i++)
#pragma unroll
                for (int j = 0; j < 4; j++)
#pragma unroll
                    for (int r = 0; r < 4; r++) {
                        macc[i][j][r] += cacc[i][j][r];
                        cacc[i][j][r] = 0.f;
                    }
        }
        __syncthreads();
    }
#undef PREFETCH

    // ---- epilogue: bias + relu, write g_h[oc][p] ----------------------------
#pragma unroll
    for (int i = 0; i < 2; i++) {
        int m_tile = warp_m * 2 + i;
        int r0 = oc0 + m_tile * 16 + (lane >> 2);
        float bb0 = __ldg(bias + r0);
        float bb1 = __ldg(bias + r0 + 8);
        float* gp0 = g_h + (size_t)r0 * P_TOT;
        float* gp1 = g_h + (size_t)(r0 + 8) * P_TOT;
#pragma unroll
        for (int j = 0; j < 4; j++) {
            int n_tile = warp_n * 4 + j;
            int c0 = p0 + n_tile * 8 + 2 * (lane & 3);
            if (c0 < P_TOT) {
                float2 v0, v1;
                v0.x = fmaxf(macc[i][j][0] + bb0, 0.f);
                v0.y = fmaxf(macc[i][j][1] + bb0, 0.f);
                v1.x = fmaxf(macc[i][j][2] + bb1, 0.f);
                v1.y = fmaxf(macc[i][j][3] + bb1, 0.f);
                *(float2*)(gp0 + c0) = v0;
                *(float2*)(gp1 + c0) = v1;
            }
        }
    }
}

// ------------------------------- heads (1x1 convs) ---------------------------
__global__ void k_heads(const float* __restrict__ sw, const float* __restrict__ sb,
                        const float* __restrict__ lw, const float* __restrict__ lb,
                        float* __restrict__ out) {
    __shared__ float hs[16][68];
    __shared__ float ws[54][68];
    const int p0 = blockIdx.x * 16;
    const int t  = threadIdx.x;    // 864 threads
    const int pl = t & 15;
    const int ch = t >> 4;         // 0..53
    float acc = 0.f;

    for (int c0 = 0; c0 < 512; c0 += 64) {
        for (int e = t; e < 54 * 64; e += 864) {
            int cc  = e & 63;
            int chh = e >> 6;
            float v = (chh < 18) ? sw[chh * 512 + c0 + cc]
                                 : lw[(chh - 18) * 512 + c0 + cc];
            ws[chh][cc] = v;
        }
        for (int e = t; e < 16 * 64; e += 864) {
            int pp = e & 15;
            int cc = e >> 4;
            hs[pp][cc] = g_h[(size_t)(c0 + cc) * P_TOT + p0 + pp];
        }
        __syncthreads();
#pragma unroll
        for (int c4 = 0; c4 < 64; c4 += 4) {
            float4 wv = *(const float4*)&ws[ch][c4];
            float4 hv = *(const float4*)&hs[pl][c4];
            acc += wv.x * hv.x + wv.y * hv.y + wv.z * hv.z + wv.w * hv.w;
        }
        __syncthreads();
    }
    int pg = p0 + pl;
    if (ch < 18) {
        acc += sb[ch];
        int anc = ch >> 1, d = ch & 1;
        out[SCORE_OFF + ((size_t)pg * 9 + anc) * 2 + d] = acc;
    } else {
        int lc = ch - 18;
        acc += lb[lc];
        int anc = lc >> 2, d = lc & 3;
        out[LOC_OFF + ((size_t)pg * 9 + anc) * 4 + d] = acc;
    }
}

// ------------------------------- proposals -----------------------------------
__device__ __forceinline__ float scal_to_f(const int* p) {
    int v = *p;
    if (v > 0 && v < 10000000) return (float)v;
    return __int_as_float(v);
}

__global__ void k_prop(const float* __restrict__ out, const int* ihp, const int* iwp) {
    int a = blockIdx.x * 256 + threadIdx.x;
    if (a >= NANC) return;
    float imh = scal_to_f(ihp);
    float imw = scal_to_f(iwp);

    int t  = a % 9;
    int p  = a / 9;
    int y  = p / WWID;
    int xi = p - y * WWID;
    int ri = t / 3, si = t - ri * 3;
    double r = (ri == 0) ? 0.5 : (ri == 1 ? 1.0 : 2.0);
    double s = (si == 0) ? 8.0 : (si == 1 ? 16.0 : 32.0);
    double hbd = 16.0 * s * sqrt(r);
    double wbd = 16.0 * s * sqrt(1.0 / r);
    float ay1 = (float)y * 16.f + (float)(8.0 - hbd / 2.0);
    float ax1 = (float)xi * 16.f + (float)(8.0 - wbd / 2.0);
    float ay2 = (float)y * 16.f + (float)(8.0 + hbd / 2.0);
    float ax2 = (float)xi * 16.f + (float)(8.0 + wbd / 2.0);

    float dy = out[LOC_OFF + (size_t)a * 4 + 0];
    float dx = out[LOC_OFF + (size_t)a * 4 + 1];
    float dh = out[LOC_OFF + (size_t)a * 4 + 2];
    float dw = out[LOC_OFF + (size_t)a * 4 + 3];

    float ah = ay2 - ay1, aw = ax2 - ax1;
    float cy = ay1 + 0.5f * ah, cx = ax1 + 0.5f * aw;
    float cy2 = dy * ah + cy, cx2 = dx * aw + cx;
    float h2 = expf(dh) * ah, w2 = expf(dw) * aw;
    float r0 = cy2 - 0.5f * h2, r1 = cx2 - 0.5f * w2;
    float r2 = cy2 + 0.5f * h2, r3 = cx2 + 0.5f * w2;
    r0 = fminf(fmaxf(r0, 0.f), imh);
    r1 = fminf(fmaxf(r1, 0.f), imw);
    r2 = fminf(fmaxf(r2, 0.f), imh);
    r3 = fminf(fmaxf(r3, 0.f), imw);
    bool valid = (r2 - r0 >= 16.f) && (r3 - r1 >= 16.f);

    float s0 = out[SCORE_OFF + (size_t)a * 2 + 0];
    float s1 = out[SCORE_OFF + (size_t)a * 2 + 1];
    float m = fmaxf(s0, s1);
    float e0 = expf(s0 - m), e1 = expf(s1 - m);
    float fg = e1 / (e0 + e1);
    float sc = valid ? fg : __int_as_float(0xff800000);

    u32 bits = __float_as_uint(sc);
    u32 fs = bits ^ ((bits & 0x80000000u) ? 0xFFFFFFFFu : 0x80000000u);
    g_keys[a] = ((u64)fs << 32) | (u32)(~(u32)a);
    g_roi[(size_t)a * 4 + 0] = r0;
    g_roi[(size_t)a * 4 + 1] = r1;
    g_roi[(size_t)a * 4 + 2] = r2;
    g_roi[(size_t)a * 4 + 3] = r3;
}

// --------------------- top-6000 selection (radix select) ---------------------
__global__ void k_clear() {
    int t = threadIdx.x;
    if (t < 1024) g_hist[t] = 0;
    if (t == 0) { g_prefix = 0u; g_count_gt = 0; g_ccount = 0; }
}

__global__ void k_hist(int L) {
    __shared__ int sh[256];
    int t = threadIdx.x;
    sh[t] = 0;
    __syncthreads();
    int idx = blockIdx.x * 256 + t;
    if (idx < NANC) {
        u32 fs = (u32)(g_keys[idx] >> 32);
        bool ok = true;
        if (L > 0) {
            int shf = 32 - 8 * L;
            ok = (fs >> shf) == (g_prefix >> shf);
        }
        if (ok) atomicAdd(&sh[(fs >> (24 - 8 * L)) & 255], 1);
    }
    __syncthreads();
    if (sh[t]) atomicAdd(&g_hist[L * 256 + t], sh[t]);
}

__global__ void k_scan(int L) {
    int need = NPRE - g_count_gt;
    int above = 0;
    int chosen = 0;
    for (int b = 255; b >= 0; b--) {
        int c = g_hist[L * 256 + b];
        if (above + c >= need) { chosen = b; break; }
        above += c;
    }
    g_prefix |= (u32)chosen << (24 - 8 * L);
    g_count_gt += above;
}

__global__ void k_compact() {
    int idx = blockIdx.x * 256 + threadIdx.x;
    if (idx >= NANC) return;
    u64 key = g_keys[idx];
    u32 fs = (u32)(key >> 32);
    if (fs >= g_prefix) {
        int pos = atomicAdd(&g_ccount, 1);
        if (pos < 8192) g_cand[pos] = key;
    }
}

// One-block bitonic sort (descending) of <=8192 candidate keys.
__global__ void k_sort(float* __restrict__ out) {
    extern __shared__ u64 sk[];
    int t = threadIdx.x;   // 1024
    int C = g_ccount;
    if (C > 8192) C = 8192;
    for (int i = t; i < 8192; i += 1024) sk[i] = (i < C) ? g_cand[i] : 0ULL;
    __syncthreads();
    for (int k = 2; k <= 8192; k <<= 1) {
        for (int j = k >> 1; j > 0; j >>= 1) {
            for (int i = t; i < 8192; i += 1024) {
                int ixj = i ^ j;
                if (ixj > i) {
                    u64 a = sk[i], b = sk[ixj];
                    bool descBlock = ((i & k) == 0);
                    bool sw = descBlock ? (a < b) : (a > b);
                    if (sw) { sk[i] = b; sk[ixj] = a; }
                }
            }
            __syncthreads();
        }
    }
    for (int i = t; i < NPRE; i += 1024) {
        u64 key = sk[i];
        u32 fs = (u32)(key >> 32);
        u32 idx = ~(u32)key;
        float b0 = 0.f, b1 = 0.f, b2 = 0.f, b3 = 0.f;
        if (key != 0ULL && idx < NANC) {
            b0 = g_roi[(size_t)idx * 4 + 0];
            b1 = g_roi[(size_t)idx * 4 + 1];
            b2 = g_roi[(size_t)idx * 4 + 2];
            b3 = g_roi[(size_t)idx * 4 + 3];
        }
        g_sboxes[i * 4 + 0] = b0;
        g_sboxes[i * 4 + 1] = b1;
        g_sboxes[i * 4 + 2] = b2;
        g_sboxes[i * 4 + 3] = b3;
        g_svalid[i] = (fs > FS_NEGINF) ? 1 : 0;
    }
    for (int i = t; i < NPOST * 4; i += 1024) out[ROIS_OFF + i] = 0.f;
}

// ------------------------------- NMS -----------------------------------------
__global__ void k_mask() {
    __shared__ float cy1[64], cx1[64], cy2s[64], cx2s[64], car[64];
    int t = threadIdx.x;
    int bi = blockIdx.y, bj = blockIdx.x;
    int j = bj * 64 + t;
    float jy1 = 0, jx1 = 0, jy2 = 0, jx2 = 0;
    if (j < NPRE) {
        jy1 = g_sboxes[j * 4 + 0];
        jx1 = g_sboxes[j * 4 + 1];
        jy2 = g_sboxes[j * 4 + 2];
        jx2 = g_sboxes[j * 4 + 3];
    }
    cy1[t] = jy1; cx1[t] = jx1; cy2s[t] = jy2; cx2s[t] = jx2;
    car[t] = (jy2 - jy1) * (jx2 - jx1);
    __syncthreads();
    int i = bi * 64 + t;
    if (i >= NPRE) return;
    float iy1 = g_sboxes[i * 4 + 0];
    float ix1 = g_sboxes[i * 4 + 1];
    float iy2 = g_sboxes[i * 4 + 2];
    float ix2 = g_sboxes[i * 4 + 3];
    float ar = (iy2 - iy1) * (ix2 - ix1);
    u64 word = 0;
#pragma unroll 8
    for (int jj = 0; jj < 64; jj++) {
        int jg = bj * 64 + jj;
        float ih = fmaxf(fminf(iy2, cy2s[jj]) - fmaxf(iy1, cy1[jj]), 0.f);
        float iw = fmaxf(fminf(ix2, cx2s[jj]) - fmaxf(ix1, cx1[jj]), 0.f);
        float inter = ih * iw;
        float iou = inter / (ar + car[jj] - inter + 1e-9f);
        if (jg > i && jg < NPRE && iou > 0.7f) word |= 1ULL << jj;
    }
    g_mask[(size_t)i * NW + bj] = word;
}

__device__ __forceinline__ u64 apply_valid(int w, u64 k) {
    int base = w * 64;
#pragma unroll 4
    for (int b = 0; b < 64; b++) {
        int row = base + b;
        if (row >= NPRE || !g_svalid[row]) k &= ~(1ULL << b);
    }
    return k;
}

// Producer/consumer NMS reduce: warps 1-3 prefetch 64-row mask windows into a
// 4-slot SMEM ring; warp 0 runs the serial suppression chain from SMEM.
// Early exit at 300 valid keeps.
#define RWIN 94                  // windows of 64 rows
#define RSLOT_W (64 * NW)        // u64 words per slot
__global__ void k_reduce2() {
    extern __shared__ u64 ring[];            // 4 * RSLOT_W u64
    __shared__ volatile int prod_gen[4];
    __shared__ volatile int cons_done;
    __shared__ volatile int finished;
    int t = threadIdx.x, wid = t >> 5, l = t & 31;
    if (t < 4) prod_gen[t] = -1;
    if (t == 4) { cons_done = -1; finished = 0; }
    __syncthreads();

    if (wid > 0) {
        for (int w = wid - 1; w < RWIN; w += 3) {
            int slot = w & 3;
            while (cons_done < w - 4 && !finished) { }
            if (finished) break;
            u64* dst = ring + (size_t)slot * RSLOT_W;
            const u64* src = g_mask + (size_t)w * 64 * NW;
            int rows = min(64, NPRE - w * 64);
            int total = rows * NW;
            for (int i = l; i < total; i += 32) dst[i] = src[i];
            __threadfence_block();
            __syncwarp();
            if (l == 0) prod_gen[slot] = w;
        }
    } else {
        u64 k0 = ~0ULL;
        u64 k1 = ~0ULL;
        u64 k2;
        {
            int w = l + 64;
            if (w < 93) k2 = ~0ULL;
            else if (w == 93) k2 = 0x0000FFFFFFFFFFFFULL;
            else k2 = 0ULL;
        }
        int cnt = 0;
        bool stop = false;
        for (int w = 0; w < RWIN && !stop; w++) {
            int slot = w & 3;
            while (prod_gen[slot] != w) { }
            __threadfence_block();
            const u64* win = ring + (size_t)slot * RSLOT_W;
            int rows = min(64, NPRE - w * 64);
            for (int r = 0; r < rows; r++) {
                int i = w * 64 + r;
                int iw = i >> 6;
                int sl = iw >> 5;
                int src = iw & 31;
                u64 kv = (sl == 0) ? k0 : ((sl == 1) ? k1 : k2);
                u64 kw = __shfl_sync(0xffffffffu, kv, src);
                if ((kw >> (i & 63)) & 1ULL) {
                    const u64* mr = win + (size_t)r * NW;
                    u64 m0 = mr[l];
                    u64 m1 = mr[l + 32];
                    u64 m2 = (l + 64 < NW) ? mr[l + 64] : 0ULL;
                    k0 &= ~m0;
                    k1 &= ~m1;
                    k2 &= ~m2;
                    if (g_svalid[i]) cnt++;
                    if (cnt >= NPOST) { stop = true; break; }
                }
            }
            if (l == 0) cons_done = w;
        }
        if (l == 0) finished = 1;

        g_keep[l]      = apply_valid(l, k0);
        g_keep[l + 32] = apply_valid(l + 32, k1);
        if (l + 64 < NW) g_keep[l + 64] = apply_valid(l + 64, k2);
        __syncwarp();
        if (l == 0) {
            int run = 0;
            for (int w = 0; w < NW; w++) {
                g_keeppre[w] = run;
                run += __popcll(g_keep[w]);
            }
        }
    }
}

__global__ void k_final(float* __restrict__ out) {
    int i = blockIdx.x * 256 + threadIdx.x;
    if (i >= NPRE) return;
    int w = i >> 6, b = i & 63;
    u64 kw = g_keep[w];
    if (!((kw >> b) & 1ULL)) return;
    u64 below = kw & ((1ULL << b) - 1ULL);
    int pos = g_keeppre[w] + __popcll(below);
    if (pos < NPOST) {
        out[ROIS_OFF + pos * 4 + 0] = g_sboxes[i * 4 + 0];
        out[ROIS_OFF + pos * 4 + 1] = g_sboxes[i * 4 + 1];
        out[ROIS_OFF + pos * 4 + 2] = g_sboxes[i * 4 + 2];
        out[ROIS_OFF + pos * 4 + 3] = g_sboxes[i * 4 + 3];
    }
}

// ------------------------------- launch --------------------------------------
extern "C" void kernel_launch(void* const* d_in, const int* in_sizes, int n_in,
                              void* d_out, int out_size) {
    const float* x  = (const float*)d_in[0];
    const float* w1 = (const float*)d_in[1];
    const float* b1 = (const float*)d_in[2];
    const float* sw = (const float*)d_in[3];
    const float* sb = (const float*)d_in[4];
    const float* lw = (const float*)d_in[5];
    const float* lb = (const float*)d_in[6];
    const int* ihp  = (const int*)d_in[7];
    const int* iwp  = (const int*)d_in[8];
    float* out = (float*)d_out;

    // launch order puts k_conv_mma in the ncu capture slot (our 4th launch)
    k_clear<<<1, 1024>>>();
    k_split_w<<<dim3(144, 4), 256>>>(w1);
    k_split_x<<<7600, 256>>>(x);

    cudaFuncSetAttribute(k_conv_mma, cudaFuncAttributeMaxDynamicSharedMemorySize,
                         2 * STG_BYTES);
    k_conv_mma<<<dim3(119, 4), 512, 2 * STG_BYTES>>>(b1);

    k_heads<<<950, 864>>>(sw, sb, lw, lb, out);
    k_prop<<<(NANC + 255) / 256, 256>>>(out, ihp, iwp);

    for (int L = 0; L < 4; L++) {
        k_hist<<<(NANC + 255) / 256, 256>>>(L);
        k_scan<<<1, 1>>>(L);
    }
    k_compact<<<(NANC + 255) / 256, 256>>>();

    cudaFuncSetAttribute(k_sort, cudaFuncAttributeMaxDynamicSharedMemorySize, 65536);
    k_sort<<<1, 1024, 65536>>>(out);

    k_mask<<<dim3(NW, NW), 64>>>();

    cudaFuncSetAttribute(k_reduce2, cudaFuncAttributeMaxDynamicSharedMemorySize,
                         4 * RSLOT_W * 8);
    k_reduce2<<<1, 128, 4 * RSLOT_W * 8>>>();
    k_final<<<(NPRE + 255) / 256, 256>>>(out);
}

// round 17
// speedup vs baseline: 2.3093x; 1.0708x over previous
#include <cuda_runtime.h>
#include <stdint.h>
#include <math.h>

typedef unsigned int u32;
typedef unsigned long long u64;

#define HH 100
#define WWID 152
#define P_TOT 15200
#define NANC 136800
#define NPRE 6000
#define NPOST 300
#define NW 94            // ceil(6000/64)
#define LOC_OFF 0
#define SCORE_OFF 547200
#define ROIS_OFF 820800
#define FS_NEGINF 0x007FFFFFu
#define NPB 119          // p-blocks
#define NCHUNK 144       // 4608 / 32

// ------------------- scratch (static device globals: no allocation) ---------
__device__ float g_h[512 * P_TOT];          // conv1 output, [oc][p]
__device__ float g_wfhi[4 * 144 * 4096];    // pre-split+fragment-permuted weights
__device__ float g_wflo[4 * 144 * 4096];
__device__ float g_bfhi[(size_t)NPB * NCHUNK * 4096]; // pre-im2col B, frag order
__device__ float g_bflo[(size_t)NPB * NCHUNK * 4096];
__device__ float g_roi[NANC * 4];           // clipped boxes per anchor
__device__ u64   g_keys[NANC];              // (flipped score)<<32 | ~index
__device__ int   g_hist[1024];              // 4 levels x 256 bins
__device__ u32   g_prefix;
__device__ int   g_count_gt;
__device__ int   g_ccount;
__device__ u64   g_cand[8192];
__device__ float g_sboxes[NPRE * 4];        // top-6000 boxes, score order
__device__ unsigned char g_svalid[NPRE + 64];
__device__ u64   g_mask[(size_t)NPRE * NW]; // NMS suppression bitmatrix
__device__ u64   g_keep[NW];
__device__ int   g_keeppre[NW];

// ========================= tf32 helpers (mma.sync path) ======================
__device__ __forceinline__ void split_tf32(float a, uint32_t& hi, uint32_t& lo) {
    uint32_t h;
    asm("cvt.rna.tf32.f32 %0, %1;" : "=r"(h) : "f"(a));
    float l = a - __uint_as_float(h);
    uint32_t lb;
    asm("cvt.rna.tf32.f32 %0, %1;" : "=r"(lb) : "f"(l));
    hi = h; lo = lb;
}

__device__ __forceinline__ void mma8(float* c, const uint32_t* a, const uint32_t* b) {
    asm volatile(
        "mma.sync.aligned.m16n8k8.row.col.f32.tf32.tf32.f32 "
        "{%0,%1,%2,%3},{%4,%5,%6,%7},{%8,%9},{%0,%1,%2,%3};"
        : "+f"(c[0]), "+f"(c[1]), "+f"(c[2]), "+f"(c[3])
        : "r"(a[0]), "r"(a[1]), "r"(a[2]), "r"(a[3]), "r"(b[0]), "r"(b[1]));
}

__device__ __forceinline__ uint32_t smem_u32(const void* p) {
    uint32_t a;
    asm("{ .reg .u64 t; cvta.to.shared.u64 t, %1; cvt.u32.u64 %0, t; }" : "=r"(a) : "l"(p));
    return a;
}
__device__ __forceinline__ void cpa16(uint32_t dst, const void* src) {
    asm volatile("cp.async.ca.shared.global [%0], [%1], 16;" :: "r"(dst), "l"(src));
}
#define CPA_COMMIT() asm volatile("cp.async.commit_group;" ::: "memory")

// stage byte layout: AHI 0, ALO 16384, BHI 32768, BLO 49152; stage = 64KB
#define STG_BYTES 65536
#define STG_FLOATS 16384

// --------------------- weight pre-split + fragment permute -------------------
__global__ void k_split_w(const float* __restrict__ w) {
    int ch  = blockIdx.x;          // 0..143
    int ocb = blockIdx.y;          // 0..3
#pragma unroll
    for (int s = 0; s < 4; s++) {
        int e0 = (threadIdx.x + s * 256) * 4;   // 0..4092
        float hi4[4], lo4[4];
#pragma unroll
        for (int r = 0; r < 4; r++) {
            int e  = e0 + r;
            int rg = e & 3;
            int ln = (e >> 2) & 31;
            int g  = e >> 7;          // 0..31
            int m_tile = g >> 2;      // 0..7
            int kstep  = g & 3;
            int ocl = m_tile * 16 + (rg & 1) * 8 + (ln >> 2);
            int kin = kstep * 8 + ((rg >> 1) & 1) * 4 + (ln & 3);
            float v = w[(size_t)(ocb * 128 + ocl) * 4608 + ch * 32 + kin];
            uint32_t h, l;
            split_tf32(v, h, l);
            hi4[r] = __uint_as_float(h);
            lo4[r] = __uint_as_float(l);
        }
        size_t base = ((size_t)ocb * 144 + ch) * 4096 + e0;
        *(float4*)(g_wfhi + base) = make_float4(hi4[0], hi4[1], hi4[2], hi4[3]);
        *(float4*)(g_wflo + base) = make_float4(lo4[0], lo4[1], lo4[2], lo4[3]);
    }
}

// -------- im2col + tf32 split + fragment permute, materialized to global ----
// e index inside a (pb, ch) tile: e = g*64 + ln*2 + rg where g = n_tile*4+kstep,
// ln = nn*4 + (kc&3), rg = kc>>2, pl = n_tile*8+nn, kin = kstep*8+kc.
__global__ void k_im2col(const float* __restrict__ x) {
    int ch = blockIdx.x;      // 0..143
    int pb = blockIdx.y;      // 0..118
    int t  = threadIdx.x;     // 512
    size_t base = ((size_t)pb * NCHUNK + ch) * 4096;
#pragma unroll
    for (int s = 0; s < 8; s++) {
        int e = t + s * 512;
        int rg = e & 1;
        int ln = (e >> 1) & 31;
        int g  = e >> 6;          // 0..63
        int kstep  = g & 3;
        int n_tile = g >> 2;      // 0..15
        int nn = ln >> 2;
        int kc = (ln & 3) | (rg << 2);
        int pl = (n_tile << 3) | nn;
        int kin = (kstep << 3) | kc;
        int k = ch * 32 + kin;
        int ic = k / 9;
        int r = k - ic * 9;
        int dy = r / 3 - 1;
        int dx = r - (r / 3) * 3 - 1;
        int p = pb * 128 + pl;
        int y = p / WWID;
        int xx = p - y * WWID;
        int yy = y + dy;
        int x2 = xx + dx;
        float v = 0.f;
        if (p < P_TOT && (unsigned)yy < HH && (unsigned)x2 < WWID)
            v = __ldg(x + (size_t)ic * P_TOT + yy * WWID + x2);
        uint32_t h, l;
        split_tf32(v, h, l);
        g_bfhi[base + e] = __uint_as_float(h);
        g_bflo[base + e] = __uint_as_float(l);
    }
}

// ---- conv 3x3: mma.sync tf32x3, windowed accum, cp.async 3-stage, 16 warps --
// All operands pre-permuted in global; per chunk each thread issues 8 cpa16.
__global__ void __launch_bounds__(512, 1)
k_conv_mma(const float* __restrict__ bias) {
    extern __shared__ float sm[];
    const uint32_t sbase = smem_u32(sm);

    const int t = threadIdx.x;
    const int wid = t >> 5;
    const int lane = t & 31;
    const int ocb = blockIdx.x;            // 0..3 (fastest: B shared in-wave)
    const int pb  = blockIdx.y;            // 0..118
    const int p0  = pb * 128;
    const int oc0 = ocb * 128;
    const int warp_m = wid >> 2;   // 0..3 (32 oc each)
    const int warp_n = wid & 3;    // 0..3 (32 p each)

    const size_t abase = (size_t)ocb * NCHUNK * 4096 + t * 8;
    const size_t bbase = (size_t)pb  * NCHUNK * 4096 + t * 8;

    float macc[2][4][4];
    float cacc[2][4][4];
#pragma unroll
    for (int i = 0; i < 2; i++)
#pragma unroll
        for (int j = 0; j < 4; j++)
#pragma unroll
            for (int r = 0; r < 4; r++) { macc[i][j][r] = 0.f; cacc[i][j][r] = 0.f; }

#define PREFETCH(CH, STG_OFF) do {                                             \
        const int _ch = (CH);                                                  \
        const uint32_t _stg = sbase + (STG_OFF);                               \
        const float* _a = g_wfhi + abase + (size_t)_ch * 4096;                 \
        const float* _al = g_wflo + abase + (size_t)_ch * 4096;                \
        const float* _b = g_bfhi + bbase + (size_t)_ch * 4096;                 \
        const float* _bl = g_bflo + bbase + (size_t)_ch * 4096;                \
        cpa16(_stg + t * 32,              _a);                                 \
        cpa16(_stg + t * 32 + 16,         _a + 4);                             \
        cpa16(_stg + 16384 + t * 32,      _al);                                \
        cpa16(_stg + 16384 + t * 32 + 16, _al + 4);                            \
        cpa16(_stg + 32768 + t * 32,      _b);                                 \
        cpa16(_stg + 32768 + t * 32 + 16, _b + 4);                             \
        cpa16(_stg + 49152 + t * 32,      _bl);                                \
        cpa16(_stg + 49152 + t * 32 + 16, _bl + 4);                            \
    } while (0)

    PREFETCH(0, 0u);
    CPA_COMMIT();
    PREFETCH(1, STG_BYTES);
    CPA_COMMIT();

    for (int ch = 0; ch < NCHUNK; ch++) {
        if (ch + 2 < NCHUNK) {
            PREFETCH(ch + 2, (u32)(((ch + 2) % 3) * STG_BYTES));
            CPA_COMMIT();
            asm volatile("cp.async.wait_group 2;" ::: "memory");
        } else if (ch + 1 < NCHUNK) {
            asm volatile("cp.async.wait_group 1;" ::: "memory");
        } else {
            asm volatile("cp.async.wait_group 0;" ::: "memory");
        }
        __syncthreads();

        float* base = sm + (ch % 3) * STG_FLOATS;
        float* a_hi = base;
        float* a_lo = base + 4096;
        float* b_hi = base + 8192;
        float* b_lo = base + 12288;
#pragma unroll
        for (int ks = 0; ks < 4; ks++) {
            uint32_t Ah[2][4], Al[2][4], Bh[4][2], Bl[4][2];
#pragma unroll
            for (int i = 0; i < 2; i++) {
                int m_tile = warp_m * 2 + i;
                int boff = (((m_tile * 4 + ks) * 32) + lane) * 4;
                float4 vh = *(const float4*)(a_hi + boff);
                float4 vl = *(const float4*)(a_lo + boff);
                Ah[i][0] = __float_as_uint(vh.x); Ah[i][1] = __float_as_uint(vh.y);
                Ah[i][2] = __float_as_uint(vh.z); Ah[i][3] = __float_as_uint(vh.w);
                Al[i][0] = __float_as_uint(vl.x); Al[i][1] = __float_as_uint(vl.y);
                Al[i][2] = __float_as_uint(vl.z); Al[i][3] = __float_as_uint(vl.w);
            }
#pragma unroll
            for (int j = 0; j < 4; j++) {
                int n_tile = warp_n * 4 + j;
                int boff = (((n_tile * 4 + ks) * 32) + lane) * 2;
                float2 vh = *(const float2*)(b_hi + boff);
                float2 vl = *(const float2*)(b_lo + boff);
                Bh[j][0] = __float_as_uint(vh.x); Bh[j][1] = __float_as_uint(vh.y);
                Bl[j][0] = __float_as_uint(vl.x); Bl[j][1] = __float_as_uint(vl.y);
            }
#pragma unroll
            for (int i = 0; i < 2; i++)
#pragma unroll
                for (int j = 0; j < 4; j++) mma8(cacc[i][j], Ah[i], Bh[j]);
#pragma unroll
            for (int i = 0; i < 2; i++)
#pragma unroll
                for (int j = 0; j < 4; j++) mma8(cacc[i][j], Ah[i], Bl[j]);
#pragma unroll
            for (int i = 0; i < 2; i++)
#pragma unroll
                for (int j = 0; j < 4; j++) mma8(cacc[i][j], Al[i], Bh[j]);
        }
        if (ch & 1) {
#pragma unroll
            for (int i = 0; i < 2; i++)
#pragma unroll
                for (int j = 0; j < 4; j++)
#pragma unroll
                    for (int r = 0; r < 4; r++) {
                        macc[i][j][r] += cacc[i][j][r];
                        cacc[i][j][r] = 0.f;
                    }
        }
        __syncthreads();
    }
#undef PREFETCH

    // ---- epilogue: bias + relu, write g_h[oc][p] ----------------------------
#pragma unroll
    for (int i = 0; i < 2; i++) {
        int m_tile = warp_m * 2 + i;
        int r0 = oc0 + m_tile * 16 + (lane >> 2);
        float bb0 = __ldg(bias + r0);
        float bb1 = __ldg(bias + r0 + 8);
        float* gp0 = g_h + (size_t)r0 * P_TOT;
        float* gp1 = g_h + (size_t)(r0 + 8) * P_TOT;
#pragma unroll
        for (int j = 0; j < 4; j++) {
            int n_tile = warp_n * 4 + j;
            int c0 = p0 + n_tile * 8 + 2 * (lane & 3);
            if (c0 < P_TOT) {
                float2 v0, v1;
                v0.x = fmaxf(macc[i][j][0] + bb0, 0.f);
                v0.y = fmaxf(macc[i][j][1] + bb0, 0.f);
                v1.x = fmaxf(macc[i][j][2] + bb1, 0.f);
                v1.y = fmaxf(macc[i][j][3] + bb1, 0.f);
                *(float2*)(gp0 + c0) = v0;
                *(float2*)(gp1 + c0) = v1;
            }
        }
    }
}

// ------------------------------- heads (1x1 convs) ---------------------------
__global__ void k_heads(const float* __restrict__ sw, const float* __restrict__ sb,
                        const float* __restrict__ lw, const float* __restrict__ lb,
                        float* __restrict__ out) {
    __shared__ float hs[16][68];
    __shared__ float ws[54][68];
    const int p0 = blockIdx.x * 16;
    const int t  = threadIdx.x;    // 864 threads
    const int pl = t & 15;
    const int ch = t >> 4;         // 0..53
    float acc = 0.f;

    for (int c0 = 0; c0 < 512; c0 += 64) {
        for (int e = t; e < 54 * 64; e += 864) {
            int cc  = e & 63;
            int chh = e >> 6;
            float v = (chh < 18) ? sw[chh * 512 + c0 + cc]
                                 : lw[(chh - 18) * 512 + c0 + cc];
            ws[chh][cc] = v;
        }
        for (int e = t; e < 16 * 64; e += 864) {
            int pp = e & 15;
            int cc = e >> 4;
            hs[pp][cc] = g_h[(size_t)(c0 + cc) * P_TOT + p0 + pp];
        }
        __syncthreads();
#pragma unroll
        for (int c4 = 0; c4 < 64; c4 += 4) {
            float4 wv = *(const float4*)&ws[ch][c4];
            float4 hv = *(const float4*)&hs[pl][c4];
            acc += wv.x * hv.x + wv.y * hv.y + wv.z * hv.z + wv.w * hv.w;
        }
        __syncthreads();
    }
    int pg = p0 + pl;
    if (ch < 18) {
        acc += sb[ch];
        int anc = ch >> 1, d = ch & 1;
        out[SCORE_OFF + ((size_t)pg * 9 + anc) * 2 + d] = acc;
    } else {
        int lc = ch - 18;
        acc += lb[lc];
        int anc = lc >> 2, d = lc & 3;
        out[LOC_OFF + ((size_t)pg * 9 + anc) * 4 + d] = acc;
    }
}

// ------------------------------- proposals -----------------------------------
__device__ __forceinline__ float scal_to_f(const int* p) {
    int v = *p;
    if (v > 0 && v < 10000000) return (float)v;
    return __int_as_float(v);
}

__global__ void k_prop(const float* __restrict__ out, const int* ihp, const int* iwp) {
    int a = blockIdx.x * 256 + threadIdx.x;
    if (a >= NANC) return;
    float imh = scal_to_f(ihp);
    float imw = scal_to_f(iwp);

    int t  = a % 9;
    int p  = a / 9;
    int y  = p / WWID;
    int xi = p - y * WWID;
    int ri = t / 3, si = t - ri * 3;
    double r = (ri == 0) ? 0.5 : (ri == 1 ? 1.0 : 2.0);
    double s = (si == 0) ? 8.0 : (si == 1 ? 16.0 : 32.0);
    double hbd = 16.0 * s * sqrt(r);
    double wbd = 16.0 * s * sqrt(1.0 / r);
    float ay1 = (float)y * 16.f + (float)(8.0 - hbd / 2.0);
    float ax1 = (float)xi * 16.f + (float)(8.0 - wbd / 2.0);
    float ay2 = (float)y * 16.f + (float)(8.0 + hbd / 2.0);
    float ax2 = (float)xi * 16.f + (float)(8.0 + wbd / 2.0);

    float dy = out[LOC_OFF + (size_t)a * 4 + 0];
    float dx = out[LOC_OFF + (size_t)a * 4 + 1];
    float dh = out[LOC_OFF + (size_t)a * 4 + 2];
    float dw = out[LOC_OFF + (size_t)a * 4 + 3];

    float ah = ay2 - ay1, aw = ax2 - ax1;
    float cy = ay1 + 0.5f * ah, cx = ax1 + 0.5f * aw;
    float cy2 = dy * ah + cy, cx2 = dx * aw + cx;
    float h2 = expf(dh) * ah, w2 = expf(dw) * aw;
    float r0 = cy2 - 0.5f * h2, r1 = cx2 - 0.5f * w2;
    float r2 = cy2 + 0.5f * h2, r3 = cx2 + 0.5f * w2;
    r0 = fminf(fmaxf(r0, 0.f), imh);
    r1 = fminf(fmaxf(r1, 0.f), imw);
    r2 = fminf(fmaxf(r2, 0.f), imh);
    r3 = fminf(fmaxf(r3, 0.f), imw);
    bool valid = (r2 - r0 >= 16.f) && (r3 - r1 >= 16.f);

    float s0 = out[SCORE_OFF + (size_t)a * 2 + 0];
    float s1 = out[SCORE_OFF + (size_t)a * 2 + 1];
    float m = fmaxf(s0, s1);
    float e0 = expf(s0 - m), e1 = expf(s1 - m);
    float fg = e1 / (e0 + e1);
    float sc = valid ? fg : __int_as_float(0xff800000);

    u32 bits = __float_as_uint(sc);
    u32 fs = bits ^ ((bits & 0x80000000u) ? 0xFFFFFFFFu : 0x80000000u);
    g_keys[a] = ((u64)fs << 32) | (u32)(~(u32)a);
    g_roi[(size_t)a * 4 + 0] = r0;
    g_roi[(size_t)a * 4 + 1] = r1;
    g_roi[(size_t)a * 4 + 2] = r2;
    g_roi[(size_t)a * 4 + 3] = r3;
}

// --------------------- top-6000 selection (radix select) ---------------------
__global__ void k_clear() {
    int t = threadIdx.x;
    if (t < 1024) g_hist[t] = 0;
    if (t == 0) { g_prefix = 0u; g_count_gt = 0; g_ccount = 0; }
}

__global__ void k_hist(int L) {
    __shared__ int sh[256];
    int t = threadIdx.x;
    sh[t] = 0;
    __syncthreads();
    int idx = blockIdx.x * 256 + t;
    if (idx < NANC) {
        u32 fs = (u32)(g_keys[idx] >> 32);
        bool ok = true;
        if (L > 0) {
            int shf = 32 - 8 * L;
            ok = (fs >> shf) == (g_prefix >> shf);
        }
        if (ok) atomicAdd(&sh[(fs >> (24 - 8 * L)) & 255], 1);
    }
    __syncthreads();
    if (sh[t]) atomicAdd(&g_hist[L * 256 + t], sh[t]);
}

__global__ void k_scan(int L) {
    int need = NPRE - g_count_gt;
    int above = 0;
    int chosen = 0;
    for (int b = 255; b >= 0; b--) {
        int c = g_hist[L * 256 + b];
        if (above + c >= need) { chosen = b; break; }
        above += c;
    }
    g_prefix |= (u32)chosen << (24 - 8 * L);
    g_count_gt += above;
}

__global__ void k_compact() {
    int idx = blockIdx.x * 256 + threadIdx.x;
    if (idx >= NANC) return;
    u64 key = g_keys[idx];
    u32 fs = (u32)(key >> 32);
    if (fs >= g_prefix) {
        int pos = atomicAdd(&g_ccount, 1);
        if (pos < 8192) g_cand[pos] = key;
    }
}

// One-block bitonic sort (descending) of <=8192 candidate keys.
__global__ void k_sort(float* __restrict__ out) {
    extern __shared__ u64 sk[];
    int t = threadIdx.x;   // 1024
    int C = g_ccount;
    if (C > 8192) C = 8192;
    for (int i = t; i < 8192; i += 1024) sk[i] = (i < C) ? g_cand[i] : 0ULL;
    __syncthreads();
    for (int k = 2; k <= 8192; k <<= 1) {
        for (int j = k >> 1; j > 0; j >>= 1) {
            for (int i = t; i < 8192; i += 1024) {
                int ixj = i ^ j;
                if (ixj > i) {
                    u64 a = sk[i], b = sk[ixj];
                    bool descBlock = ((i & k) == 0);
                    bool sw = descBlock ? (a < b) : (a > b);
                    if (sw) { sk[i] = b; sk[ixj] = a; }
                }
            }
            __syncthreads();
        }
    }
    for (int i = t; i < NPRE; i += 1024) {
        u64 key = sk[i];
        u32 fs = (u32)(key >> 32);
        u32 idx = ~(u32)key;
        float b0 = 0.f, b1 = 0.f, b2 = 0.f, b3 = 0.f;
        if (key != 0ULL && idx < NANC) {
            b0 = g_roi[(size_t)idx * 4 + 0];
            b1 = g_roi[(size_t)idx * 4 + 1];
            b2 = g_roi[(size_t)idx * 4 + 2];
            b3 = g_roi[(size_t)idx * 4 + 3];
        }
        g_sboxes[i * 4 + 0] = b0;
        g_sboxes[i * 4 + 1] = b1;
        g_sboxes[i * 4 + 2] = b2;
        g_sboxes[i * 4 + 3] = b3;
        g_svalid[i] = (fs > FS_NEGINF) ? 1 : 0;
    }
    for (int i = t; i < NPOST * 4; i += 1024) out[ROIS_OFF + i] = 0.f;
}

// ------------------------------- NMS -----------------------------------------
__global__ void k_mask() {
    __shared__ float cy1[64], cx1[64], cy2s[64], cx2s[64], car[64];
    int t = threadIdx.x;
    int bi = blockIdx.y, bj = blockIdx.x;
    int j = bj * 64 + t;
    float jy1 = 0, jx1 = 0, jy2 = 0, jx2 = 0;
    if (j < NPRE) {
        jy1 = g_sboxes[j * 4 + 0];
        jx1 = g_sboxes[j * 4 + 1];
        jy2 = g_sboxes[j * 4 + 2];
        jx2 = g_sboxes[j * 4 + 3];
    }
    cy1[t] = jy1; cx1[t] = jx1; cy2s[t] = jy2; cx2s[t] = jx2;
    car[t] = (jy2 - jy1) * (jx2 - jx1);
    __syncthreads();
    int i = bi * 64 + t;
    if (i >= NPRE) return;
    float iy1 = g_sboxes[i * 4 + 0];
    float ix1 = g_sboxes[i * 4 + 1];
    float iy2 = g_sboxes[i * 4 + 2];
    float ix2 = g_sboxes[i * 4 + 3];
    float ar = (iy2 - iy1) * (ix2 - ix1);
    u64 word = 0;
#pragma unroll 8
    for (int jj = 0; jj < 64; jj++) {
        int jg = bj * 64 + jj;
        float ih = fmaxf(fminf(iy2, cy2s[jj]) - fmaxf(iy1, cy1[jj]), 0.f);
        float iw = fmaxf(fminf(ix2, cx2s[jj]) - fmaxf(ix1, cx1[jj]), 0.f);
        float inter = ih * iw;
        float iou = inter / (ar + car[jj] - inter + 1e-9f);
        if (jg > i && jg < NPRE && iou > 0.7f) word |= 1ULL << jj;
    }
    g_mask[(size_t)i * NW + bj] = word;
}

__device__ __forceinline__ u64 apply_valid(int w, u64 k) {
    int base = w * 64;
#pragma unroll 4
    for (int b = 0; b < 64; b++) {
        int row = base + b;
        if (row >= NPRE || !g_svalid[row]) k &= ~(1ULL << b);
    }
    return k;
}

// Producer/consumer NMS reduce: warps 1-3 prefetch 64-row mask windows into a
// 4-slot SMEM ring; warp 0 runs the serial suppression chain from SMEM.
// Early exit at 300 valid keeps.
#define RWIN 94                  // windows of 64 rows
#define RSLOT_W (64 * NW)        // u64 words per slot
__global__ void k_reduce2() {
    extern __shared__ u64 ring[];            // 4 * RSLOT_W u64
    __shared__ volatile int prod_gen[4];
    __shared__ volatile int cons_done;
    __shared__ volatile int finished;
    int t = threadIdx.x, wid = t >> 5, l = t & 31;
    if (t < 4) prod_gen[t] = -1;
    if (t == 4) { cons_done = -1; finished = 0; }
    __syncthreads();

    if (wid > 0) {
        for (int w = wid - 1; w < RWIN; w += 3) {
            int slot = w & 3;
            while (cons_done < w - 4 && !finished) { }
            if (finished) break;
            u64* dst = ring + (size_t)slot * RSLOT_W;
            const u64* src = g_mask + (size_t)w * 64 * NW;
            int rows = min(64, NPRE - w * 64);
            int total = rows * NW;
            for (int i = l; i < total; i += 32) dst[i] = src[i];
            __threadfence_block();
            __syncwarp();
            if (l == 0) prod_gen[slot] = w;
        }
    } else {
        u64 k0 = ~0ULL;
        u64 k1 = ~0ULL;
        u64 k2;
        {
            int w = l + 64;
            if (w < 93) k2 = ~0ULL;
            else if (w == 93) k2 = 0x0000FFFFFFFFFFFFULL;
            else k2 = 0ULL;
        }
        int cnt = 0;
        bool stop = false;
        for (int w = 0; w < RWIN && !stop; w++) {
            int slot = w & 3;
            while (prod_gen[slot] != w) { }
            __threadfence_block();
            const u64* win = ring + (size_t)slot * RSLOT_W;
            int rows = min(64, NPRE - w * 64);
            for (int r = 0; r < rows; r++) {
                int i = w * 64 + r;
                int iw = i >> 6;
                int sl = iw >> 5;
                int src = iw & 31;
                u64 kv = (sl == 0) ? k0 : ((sl == 1) ? k1 : k2);
                u64 kw = __shfl_sync(0xffffffffu, kv, src);
                if ((kw >> (i & 63)) & 1ULL) {
                    const u64* mr = win + (size_t)r * NW;
                    u64 m0 = mr[l];
                    u64 m1 = mr[l + 32];
                    u64 m2 = (l + 64 < NW) ? mr[l + 64] : 0ULL;
                    k0 &= ~m0;
                    k1 &= ~m1;
                    k2 &= ~m2;
                    if (g_svalid[i]) cnt++;
                    if (cnt >= NPOST) { stop = true; break; }
                }
            }
            if (l == 0) cons_done = w;
        }
        if (l == 0) finished = 1;

        g_keep[l]      = apply_valid(l, k0);
        g_keep[l + 32] = apply_valid(l + 32, k1);
        if (l + 64 < NW) g_keep[l + 64] = apply_valid(l + 64, k2);
        __syncwarp();
        if (l == 0) {
            int run = 0;
            for (int w = 0; w < NW; w++) {
                g_keeppre[w] = run;
                run += __popcll(g_keep[w]);
            }
        }
    }
}

__global__ void k_final(float* __restrict__ out) {
    int i = blockIdx.x * 256 + threadIdx.x;
    if (i >= NPRE) return;
    int w = i >> 6, b = i & 63;
    u64 kw = g_keep[w];
    if (!((kw >> b) & 1ULL)) return;
    u64 below = kw & ((1ULL << b) - 1ULL);
    int pos = g_keeppre[w] + __popcll(below);
    if (pos < NPOST) {
        out[ROIS_OFF + pos * 4 + 0] = g_sboxes[i * 4 + 0];
        out[ROIS_OFF + pos * 4 + 1] = g_sboxes[i * 4 + 1];
        out[ROIS_OFF + pos * 4 + 2] = g_sboxes[i * 4 + 2];
        out[ROIS_OFF + pos * 4 + 3] = g_sboxes[i * 4 + 3];
    }
}

// ------------------------------- launch --------------------------------------
extern "C" void kernel_launch(void* const* d_in, const int* in_sizes, int n_in,
                              void* d_out, int out_size) {
    const float* x  = (const float*)d_in[0];
    const float* w1 = (const float*)d_in[1];
    const float* b1 = (const float*)d_in[2];
    const float* sw = (const float*)d_in[3];
    const float* sb = (const float*)d_in[4];
    const float* lw = (const float*)d_in[5];
    const float* lb = (const float*)d_in[6];
    const int* ihp  = (const int*)d_in[7];
    const int* iwp  = (const int*)d_in[8];
    float* out = (float*)d_out;

    // launch order keeps k_conv_mma in the ncu capture slot (4th launch)
    k_clear<<<1, 1024>>>();
    k_split_w<<<dim3(144, 4), 256>>>(w1);
    k_im2col<<<dim3(NCHUNK, NPB), 512>>>(x);

    cudaFuncSetAttribute(k_conv_mma, cudaFuncAttributeMaxDynamicSharedMemorySize,
                         3 * STG_BYTES);
    k_conv_mma<<<dim3(4, NPB), 512, 3 * STG_BYTES>>>(b1);

    k_heads<<<950, 864>>>(sw, sb, lw, lb, out);
    k_prop<<<(NANC + 255) / 256, 256>>>(out, ihp, iwp);

    for (int L = 0; L < 4; L++) {
        k_hist<<<(NANC + 255) / 256, 256>>>(L);
        k_scan<<<1, 1>>>(L);
    }
    k_compact<<<(NANC + 255) / 256, 256>>>();

    cudaFuncSetAttribute(k_sort, cudaFuncAttributeMaxDynamicSharedMemorySize, 65536);
    k_sort<<<1, 1024, 65536>>>(out);

    k_mask<<<dim3(NW, NW), 64>>>();

    cudaFuncSetAttribute(k_reduce2, cudaFuncAttributeMaxDynamicSharedMemorySize,
                         4 * RSLOT_W * 8);
    k_reduce2<<<1, 128, 4 * RSLOT_W * 8>>>();
    k_final<<<(NPRE + 255) / 256, 256>>>(out);
}